// round 13
// baseline (speedup 1.0000x reference)
#include <cuda_runtime.h>
#include <cuda_fp16.h>
#include <math.h>
#include <stdint.h>

#define BATCH 2
#define SEQ 2048
#define DMODEL 4096
#define NQH 32
#define NKVH 8
#define HDIM 128
#define NKV (NKVH * HDIM)        // 1024
#define NQKV (DMODEL + 2 * NKV)  // 6144

// ---------------- scratch (device globals; allocation-free) ----------------
__device__ __half g_xh[(size_t)BATCH * SEQ * DMODEL];
__device__ __half g_xl[(size_t)BATCH * SEQ * DMODEL];
__device__ __half g_wqkv_h[(size_t)NQKV * DMODEL];   // [6144,4096] rows: q,k,v (hi only)
__device__ __half g_wot_h[(size_t)DMODEL * DMODEL];
__device__ __half g_atth[(size_t)BATCH * SEQ * DMODEL];
__device__ __half g_attl[(size_t)BATCH * SEQ * DMODEL];

__device__ __half g_qsh[(size_t)BATCH * SEQ * NQH * HDIM];
__device__ __half g_qsl[(size_t)BATCH * SEQ * NQH * HDIM];
__device__ __half g_ksh[(size_t)BATCH * SEQ * NKV];   // hi only
__device__ __half g_vsh[(size_t)BATCH * SEQ * NKV];   // hi only

__device__ __forceinline__ uint32_t smem_to_u32(const void* p) {
    uint32_t a;
    asm("{ .reg .u64 t; cvta.to.shared.u64 t, %1; cvt.u32.u64 %0, t; }"
        : "=r"(a) : "l"(p));
    return a;
}

#define CP_ASYNC_16(dst, src) \
    asm volatile("cp.async.cg.shared.global [%0], [%1], 16;" :: "r"(dst), "l"(src) : "memory")
#define CP_COMMIT() asm volatile("cp.async.commit_group;" ::: "memory")
#define CP_WAIT_0()  asm volatile("cp.async.wait_group 0;" ::: "memory")

#define LDMATRIX_X4(r0, r1, r2, r3, addr) \
    asm volatile("ldmatrix.sync.aligned.m8n8.x4.shared.b16 {%0,%1,%2,%3}, [%4];" \
        : "=r"(r0), "=r"(r1), "=r"(r2), "=r"(r3) : "r"(addr))
#define LDMATRIX_X4_T(r0, r1, r2, r3, addr) \
    asm volatile("ldmatrix.sync.aligned.m8n8.x4.trans.shared.b16 {%0,%1,%2,%3}, [%4];" \
        : "=r"(r0), "=r"(r1), "=r"(r2), "=r"(r3) : "r"(addr))

#define MMA_F16(d, a, b0, b1) \
    asm("mma.sync.aligned.m16n8k16.row.col.f32.f16.f16.f32 " \
        "{%0,%1,%2,%3}, {%4,%5,%6,%7}, {%8,%9}, {%0,%1,%2,%3};" \
        : "+f"((d)[0]), "+f"((d)[1]), "+f"((d)[2]), "+f"((d)[3]) \
        : "r"((a)[0]), "r"((a)[1]), "r"((a)[2]), "r"((a)[3]), "r"(b0), "r"(b1))

__device__ __forceinline__ uint32_t pack2h(float a, float b) {
    __half2 t = __floats2half2_rn(a, b);
    return *reinterpret_cast<uint32_t*>(&t);
}
__device__ __forceinline__ void split_pack_h(float a, float b, uint32_t& h, uint32_t& l) {
    __half ha = __float2half_rn(a), hb = __float2half_rn(b);
    h = pack2h(__half2float(ha), __half2float(hb));
    l = pack2h(a - __half2float(ha), b - __half2float(hb));
}

// ---------------- shared GEMM mainloop (device inline) -----------------------
// TBK=64, 2 stages of 3 tiles (Ah, Al, Bh), pitch 144B; 110.6KB -> 2 CTAs/SM.
#define TBK 64
#define APITCH 144
#define TILE_B (128 * APITCH)          // 18432
#define STAGE_B (3 * TILE_B)           // 55296
#define GEMM_SMEM (2 * STAGE_B)        // 110592

struct GemmCtx {
    float acc[2][8][4];
    int lane, wid, wm, wn, bm, bn;
};

__device__ __forceinline__ void gemm_mainloop(
    GemmCtx& g, char* smem_raw,
    const __half* __restrict__ Ah, const __half* __restrict__ Al,
    const __half* __restrict__ Bh, int K)
{
    const uint32_t sbase = smem_to_u32(smem_raw);
    const int tid = threadIdx.x;
    const int lane = g.lane, wm = g.wm, wn = g.wn, bm = g.bm, bn = g.bn;

    const __half* gsrc[3] = {Ah, Al, Bh};
    const int rbase3[3] = {bm, bm, bn};

    auto issue_stage = [&](int it, int buf) {
        const int k0 = it * TBK;
#pragma unroll
        for (int t = 0; t < 3; t++) {
            const __half* gp = gsrc[t] + (size_t)rbase3[t] * K + k0;
            const uint32_t db = sbase + buf * STAGE_B + t * TILE_B;
#pragma unroll
            for (int i = 0; i < 4; i++) {
                int c = i * 256 + tid;          // 1024 chunks of 16B per tile
                int r = c >> 3, ch = c & 7;
                const void* src = gp + (size_t)r * K + ch * 8;
                uint32_t dst = db + r * APITCH + ch * 16;
                CP_ASYNC_16(dst, src);
            }
        }
        CP_COMMIT();
    };

    const int lrow = (lane & 7) + ((lane >> 3) & 1) * 8;
    const int lk   = (lane >> 4) * 8;
    const int nrow = (lane >> 4) * 8 + (lane & 7);
    const int kadd = ((lane >> 3) & 1) * 8;

    // frag loader for one k16 quarter (A hi+lo, B hi)
    auto load_q = [&](uint32_t base, int kk,
                      uint32_t a_h[2][4], uint32_t a_l[2][4], uint32_t b_h[8][2]) {
#pragma unroll
        for (int p = 0; p < 4; p++) {
            uint32_t ab = base + 2 * TILE_B +
                          (wn * 64 + p * 16 + nrow) * APITCH + (kk * 16 + kadd) * 2;
            LDMATRIX_X4(b_h[2*p][0], b_h[2*p][1], b_h[2*p+1][0], b_h[2*p+1][1], ab);
        }
#pragma unroll
        for (int mt = 0; mt < 2; mt++) {
            uint32_t aa = base + (wm * 32 + mt * 16 + lrow) * APITCH +
                          (kk * 16 + lk) * 2;
            LDMATRIX_X4(a_h[mt][0], a_h[mt][1], a_h[mt][2], a_h[mt][3], aa);
            LDMATRIX_X4(a_l[mt][0], a_l[mt][1], a_l[mt][2], a_l[mt][3],
                        aa + TILE_B);
        }
    };

#pragma unroll
    for (int mt = 0; mt < 2; mt++)
#pragma unroll
        for (int nt = 0; nt < 8; nt++)
#pragma unroll
            for (int j = 0; j < 4; j++) g.acc[mt][nt][j] = 0.f;

    const int NITER = K / TBK;   // 64
    issue_stage(0, 0);

    for (int it = 0; it < NITER; it++) {
        CP_WAIT_0();
        __syncthreads();
        if (it + 1 < NITER) issue_stage(it + 1, (it + 1) & 1);
        const uint32_t base = sbase + (it & 1) * STAGE_B;

        uint32_t ah[2][2][4], al[2][2][4], bh[2][8][2];
        load_q(base, 0, ah[0], al[0], bh[0]);
#pragma unroll
        for (int kk = 0; kk < 4; kk++) {
            const int cur = kk & 1, nxt = cur ^ 1;
            if (kk < 3) load_q(base, kk + 1, ah[nxt], al[nxt], bh[nxt]);
            // term-major: pass 1 Ah*Bh, pass 2 Al*Bh
#pragma unroll
            for (int mt = 0; mt < 2; mt++)
#pragma unroll
                for (int nt = 0; nt < 8; nt++)
                    MMA_F16(g.acc[mt][nt], ah[cur][mt], bh[cur][nt][0], bh[cur][nt][1]);
#pragma unroll
            for (int mt = 0; mt < 2; mt++)
#pragma unroll
                for (int nt = 0; nt < 8; nt++)
                    MMA_F16(g.acc[mt][nt], al[cur][mt], bh[cur][nt][0], bh[cur][nt][1]);
        }
        __syncthreads();   // protect stage buffer before next overwrite
    }
}

// ---------------- GEMM -> fp32 C (O projection) ------------------------------
__global__ __launch_bounds__(256, 2) void gemm_mma_kernel(
    const __half* __restrict__ Ah, const __half* __restrict__ Al,
    const __half* __restrict__ Bh, float* __restrict__ C, int M, int N, int K)
{
    extern __shared__ __align__(128) char smem_raw[];
    GemmCtx g;
    g.lane = threadIdx.x & 31; g.wid = threadIdx.x >> 5;
    g.wm = g.wid & 3; g.wn = g.wid >> 2;
    g.bm = blockIdx.y * 128; g.bn = blockIdx.x * 128;
    gemm_mainloop(g, smem_raw, Ah, Al, Bh, K);

    const int gr = g.lane >> 2, t2 = (g.lane & 3) * 2;
#pragma unroll
    for (int mt = 0; mt < 2; mt++) {
#pragma unroll
        for (int nt = 0; nt < 8; nt++) {
            int row = g.bm + g.wm * 32 + mt * 16 + gr;
            int col = g.bn + g.wn * 64 + nt * 8 + t2;
            *(float2*)&C[(size_t)row * N + col] =
                make_float2(g.acc[mt][nt][0], g.acc[mt][nt][1]);
            *(float2*)&C[(size_t)(row + 8) * N + col] =
                make_float2(g.acc[mt][nt][2], g.acc[mt][nt][3]);
        }
    }
}

// ---------------- fused QKV GEMM: rope/scale/split epilogue ------------------
__device__ __forceinline__ void rope_split_store_h(
    __half* oh, __half* ol,
    const float* __restrict__ fc, const float* __restrict__ fs,
    int row, int col, float v0, float v1, int stride, int coloff, float scale,
    bool want_lo)
{
    int s = row & (SEQ - 1);
    int i = (col & 127) >> 1;
    float c  = __ldg(fc + s * 64 + i);
    float sn = __ldg(fs + s * 64 + i);
    float ra = (v0 * c - v1 * sn) * scale;
    float rb = (v0 * sn + v1 * c) * scale;
    uint32_t h, l;
    split_pack_h(ra, rb, h, l);
    size_t o = (size_t)row * stride + (col - coloff);
    *(uint32_t*)(oh + o) = h;
    if (want_lo) *(uint32_t*)(ol + o) = l;
}

__global__ __launch_bounds__(256, 2) void gemm_qkv_kernel(
    const __half* __restrict__ Ah, const __half* __restrict__ Al,
    const __half* __restrict__ Bh,
    const float* __restrict__ fc, const float* __restrict__ fs,
    __half* __restrict__ qh, __half* __restrict__ ql,
    __half* __restrict__ kh, __half* __restrict__ vh, int K)
{
    extern __shared__ __align__(128) char smem_raw[];
    GemmCtx g;
    g.lane = threadIdx.x & 31; g.wid = threadIdx.x >> 5;
    g.wm = g.wid & 3; g.wn = g.wid >> 2;
    g.bm = blockIdx.y * 128; g.bn = blockIdx.x * 128;
    gemm_mainloop(g, smem_raw, Ah, Al, Bh, K);

    const int gr = g.lane >> 2, t2 = (g.lane & 3) * 2;
    const float qscale = 0.0883883476483184f;  // 1/sqrt(128)

    if (g.bn < DMODEL) {            // Q: rope + scale + split (hi+lo)
#pragma unroll
        for (int mt = 0; mt < 2; mt++)
#pragma unroll
            for (int nt = 0; nt < 8; nt++) {
                int row = g.bm + g.wm * 32 + mt * 16 + gr;
                int col = g.bn + g.wn * 64 + nt * 8 + t2;
                rope_split_store_h(qh, ql, fc, fs, row, col,
                                   g.acc[mt][nt][0], g.acc[mt][nt][1], DMODEL, 0,
                                   qscale, true);
                rope_split_store_h(qh, ql, fc, fs, row + 8, col,
                                   g.acc[mt][nt][2], g.acc[mt][nt][3], DMODEL, 0,
                                   qscale, true);
            }
    } else if (g.bn < DMODEL + NKV) {  // K: rope, hi only
#pragma unroll
        for (int mt = 0; mt < 2; mt++)
#pragma unroll
            for (int nt = 0; nt < 8; nt++) {
                int row = g.bm + g.wm * 32 + mt * 16 + gr;
                int col = g.bn + g.wn * 64 + nt * 8 + t2;
                rope_split_store_h(kh, nullptr, fc, fs, row, col,
                                   g.acc[mt][nt][0], g.acc[mt][nt][1], NKV, DMODEL,
                                   1.0f, false);
                rope_split_store_h(kh, nullptr, fc, fs, row + 8, col,
                                   g.acc[mt][nt][2], g.acc[mt][nt][3], NKV, DMODEL,
                                   1.0f, false);
            }
    } else {                            // V: hi only
#pragma unroll
        for (int mt = 0; mt < 2; mt++)
#pragma unroll
            for (int nt = 0; nt < 8; nt++) {
                int row = g.bm + g.wm * 32 + mt * 16 + gr;
                int col = g.bn + g.wn * 64 + nt * 8 + t2 - (DMODEL + NKV);
                size_t o0 = (size_t)row * NKV + col;
                *(uint32_t*)(vh + o0) = pack2h(g.acc[mt][nt][0], g.acc[mt][nt][1]);
                size_t o1 = o0 + (size_t)8 * NKV;
                *(uint32_t*)(vh + o1) = pack2h(g.acc[mt][nt][2], g.acc[mt][nt][3]);
            }
    }
}

// ---------------- fp32 -> fp16 hi/lo split (x) --------------------------------
__global__ __launch_bounds__(256) void convert_split_kernel(
    const float* __restrict__ in, __half* __restrict__ oh,
    __half* __restrict__ ol, int n4)
{
    int i = blockIdx.x * blockDim.x + threadIdx.x;
    if (i >= n4) return;
    float4 v = ((const float4*)in)[i];
    uint32_t h0, l0, h1, l1;
    split_pack_h(v.x, v.y, h0, l0);
    split_pack_h(v.z, v.w, h1, l1);
    ((uint2*)oh)[i] = make_uint2(h0, h1);
    ((uint2*)ol)[i] = make_uint2(l0, l1);
}

// ---------------- fp32 [K,N] -> transposed fp16 [N,K] (hi only) --------------
__global__ __launch_bounds__(256) void transpose_h_kernel(
    const float* __restrict__ in, __half* __restrict__ oh, int K, int N)
{
    __shared__ float tile[32][33];
    const int k0 = blockIdx.y * 32, n0 = blockIdx.x * 32;
    const int tx = threadIdx.x & 31, ty = threadIdx.x >> 5;
#pragma unroll
    for (int i = 0; i < 32; i += 8)
        tile[ty + i][tx] = in[(size_t)(k0 + ty + i) * N + n0 + tx];
    __syncthreads();
#pragma unroll
    for (int i = 0; i < 32; i += 8) {
        float v = tile[tx][ty + i];
        oh[(size_t)(n0 + ty + i) * K + k0 + tx] = __float2half_rn(v);
    }
}

// ---------------- flash attention via mma.sync (fp16, A-side split) ----------
// BM=64, 4 warps x 16 rows, 3 CTAs/SM (single K/V buffer, 69,632 B).
// Heavy causal tiles launch first; loads hidden by sibling CTAs.
#define FP 272
#define FQH 0
#define FQL 17408
#define FKH 34816
#define FVH 52224
#define FLASH_SMEM 69632

__global__ __launch_bounds__(128, 3) void flash_mma_kernel(
    const __half* __restrict__ Qh, const __half* __restrict__ Ql,
    const __half* __restrict__ Kh, const __half* __restrict__ Vh,
    __half* __restrict__ Oh, __half* __restrict__ Ol)
{
    extern __shared__ __align__(128) char sm[];
    const uint32_t sb = smem_to_u32(sm);
    const int qt = gridDim.x - 1 - blockIdx.x;   // heavy tiles first
    const int h = blockIdx.y, b = blockIdx.z;
    const int kvh = h >> 2;
    const int tid = threadIdx.x, lane = tid & 31, w = tid >> 5;
    const int q0 = qt * 64;

    const int lrow = (lane & 7) + ((lane >> 3) & 1) * 8;
    const int lk   = (lane >> 4) * 8;
    const int nrow = (lane >> 4) * 8 + (lane & 7);
    const int kadd = ((lane >> 3) & 1) * 8;
    const int trow = lane & 15;
    const int tcol = (lane >> 4) * 8;

    // Q hi/lo tile load (plain, one-time)
    {
        const size_t qoff = ((size_t)(b * SEQ + q0) * NQH + h) * HDIM;
        const uint4* gh = (const uint4*)(Qh + qoff);
        const uint4* gl = (const uint4*)(Ql + qoff);
        for (int i = tid; i < 1024; i += 128) {
            int r = i >> 4, c = i & 15;
            *(uint4*)(sm + FQH + r * FP + c * 16) = gh[(size_t)r * 512 + c];
            *(uint4*)(sm + FQL + r * FP + c * 16) = gl[(size_t)r * 512 + c];
        }
    }

    float m0 = -1e30f, m1 = -1e30f, l0 = 0.f, l1 = 0.f;
    float oacc[16][4];
#pragma unroll
    for (int nt = 0; nt < 16; nt++)
#pragma unroll
        for (int j = 0; j < 4; j++) oacc[nt][j] = 0.f;

    const int row0 = q0 + w * 16 + (lane >> 2);
    const int cb   = 2 * (lane & 3);
    const int ktiles = qt + 1;

    for (int kt = 0; kt < ktiles; kt++) {
        __syncthreads();
        {
            const size_t off = ((size_t)(b * SEQ + kt * 64) * NKVH + kvh) * HDIM;
            const uint4* gkh = (const uint4*)(Kh + off);
            const uint4* gvh = (const uint4*)(Vh + off);
            for (int i = tid; i < 1024; i += 128) {
                int r = i >> 4, c = i & 15;
                uint32_t d = r * FP + c * 16;
                size_t gg = (size_t)r * 128 + c;
                *(uint4*)(sm + FKH + d) = gkh[gg];
                *(uint4*)(sm + FVH + d) = gvh[gg];
            }
        }
        __syncthreads();

        float s[8][4];
#pragma unroll
        for (int nt = 0; nt < 8; nt++)
#pragma unroll
            for (int j = 0; j < 4; j++) s[nt][j] = 0.f;

#pragma unroll
        for (int ks = 0; ks < 8; ks++) {
            uint32_t ah[4], al[4];
            uint32_t aa = sb + FQH + (w * 16 + lrow) * FP + (ks * 16 + lk) * 2;
            LDMATRIX_X4(ah[0], ah[1], ah[2], ah[3], aa);
            LDMATRIX_X4(al[0], al[1], al[2], al[3], aa + (FQL - FQH));
            uint32_t bh[8][2];
#pragma unroll
            for (int p = 0; p < 4; p++) {
                uint32_t ba = sb + FKH + (p * 16 + nrow) * FP + (ks * 16 + kadd) * 2;
                LDMATRIX_X4(bh[2*p][0], bh[2*p][1], bh[2*p+1][0], bh[2*p+1][1], ba);
            }
#pragma unroll
            for (int nt = 0; nt < 8; nt++) MMA_F16(s[nt], ah, bh[nt][0], bh[nt][1]);
#pragma unroll
            for (int nt = 0; nt < 8; nt++) MMA_F16(s[nt], al, bh[nt][0], bh[nt][1]);
        }

        if (kt == qt) {
            const int colb = kt * 64 + cb;
#pragma unroll
            for (int nt = 0; nt < 8; nt++) {
                int c0 = colb + 8 * nt;
                if (c0 > row0)     s[nt][0] = -1e30f;
                if (c0 + 1 > row0) s[nt][1] = -1e30f;
                if (c0 > row0 + 8)     s[nt][2] = -1e30f;
                if (c0 + 1 > row0 + 8) s[nt][3] = -1e30f;
            }
        }

        float mt0 = -1e30f, mt1 = -1e30f;
#pragma unroll
        for (int nt = 0; nt < 8; nt++) {
            mt0 = fmaxf(mt0, fmaxf(s[nt][0], s[nt][1]));
            mt1 = fmaxf(mt1, fmaxf(s[nt][2], s[nt][3]));
        }
        mt0 = fmaxf(mt0, __shfl_xor_sync(0xffffffffu, mt0, 1));
        mt0 = fmaxf(mt0, __shfl_xor_sync(0xffffffffu, mt0, 2));
        mt1 = fmaxf(mt1, __shfl_xor_sync(0xffffffffu, mt1, 1));
        mt1 = fmaxf(mt1, __shfl_xor_sync(0xffffffffu, mt1, 2));
        float mn0 = fmaxf(m0, mt0), mn1 = fmaxf(m1, mt1);
        float a0 = __expf(m0 - mn0), a1 = __expf(m1 - mn1);
        float ps0 = 0.f, ps1 = 0.f;
#pragma unroll
        for (int nt = 0; nt < 8; nt++) {
            s[nt][0] = __expf(s[nt][0] - mn0);
            s[nt][1] = __expf(s[nt][1] - mn0);
            s[nt][2] = __expf(s[nt][2] - mn1);
            s[nt][3] = __expf(s[nt][3] - mn1);
            ps0 += s[nt][0] + s[nt][1];
            ps1 += s[nt][2] + s[nt][3];
        }
        ps0 += __shfl_xor_sync(0xffffffffu, ps0, 1);
        ps0 += __shfl_xor_sync(0xffffffffu, ps0, 2);
        ps1 += __shfl_xor_sync(0xffffffffu, ps1, 1);
        ps1 += __shfl_xor_sync(0xffffffffu, ps1, 2);
        l0 = l0 * a0 + ps0;  m0 = mn0;
        l1 = l1 * a1 + ps1;  m1 = mn1;
#pragma unroll
        for (int nt = 0; nt < 16; nt++) {
            oacc[nt][0] *= a0; oacc[nt][1] *= a0;
            oacc[nt][2] *= a1; oacc[nt][3] *= a1;
        }

        // O += Ph*Vh + Pl*Vh (P residual corrected; V hi only)
#pragma unroll
        for (int j = 0; j < 4; j++) {
            uint32_t ph[4], pl[4];
            split_pack_h(s[2*j][0],   s[2*j][1],   ph[0], pl[0]);
            split_pack_h(s[2*j][2],   s[2*j][3],   ph[1], pl[1]);
            split_pack_h(s[2*j+1][0], s[2*j+1][1], ph[2], pl[2]);
            split_pack_h(s[2*j+1][2], s[2*j+1][3], ph[3], pl[3]);
            uint32_t vfh[8][4];
#pragma unroll
            for (int t = 0; t < 8; t++) {
                uint32_t va = sb + FVH + (j * 16 + trow) * FP + (t * 16 + tcol) * 2;
                LDMATRIX_X4_T(vfh[t][0], vfh[t][1], vfh[t][2], vfh[t][3], va);
            }
#pragma unroll
            for (int t = 0; t < 8; t++) {
                MMA_F16(oacc[2*t],   ph, vfh[t][0], vfh[t][1]);
                MMA_F16(oacc[2*t+1], ph, vfh[t][2], vfh[t][3]);
            }
#pragma unroll
            for (int t = 0; t < 8; t++) {
                MMA_F16(oacc[2*t],   pl, vfh[t][0], vfh[t][1]);
                MMA_F16(oacc[2*t+1], pl, vfh[t][2], vfh[t][3]);
            }
        }
    }

    const float inv0 = 1.f / l0, inv1 = 1.f / l1;
    const size_t o0 = ((size_t)(b * SEQ + row0)) * DMODEL + h * HDIM + cb;
    const size_t o1 = ((size_t)(b * SEQ + row0 + 8)) * DMODEL + h * HDIM + cb;
#pragma unroll
    for (int nt = 0; nt < 16; nt++) {
        uint32_t hh, ll;
        split_pack_h(oacc[nt][0] * inv0, oacc[nt][1] * inv0, hh, ll);
        *(uint32_t*)(Oh + o0 + 8 * nt) = hh;
        *(uint32_t*)(Ol + o0 + 8 * nt) = ll;
        split_pack_h(oacc[nt][2] * inv1, oacc[nt][3] * inv1, hh, ll);
        *(uint32_t*)(Oh + o1 + 8 * nt) = hh;
        *(uint32_t*)(Ol + o1 + 8 * nt) = ll;
    }
}

// ---------------- host launcher ---------------------------------------------
extern "C" void kernel_launch(void* const* d_in, const int* in_sizes, int n_in,
                              void* d_out, int out_size)
{
    const float* x   = (const float*)d_in[0];
    const float* w_q = (const float*)d_in[1];
    const float* w_k = (const float*)d_in[2];
    const float* w_v = (const float*)d_in[3];
    const float* w_o = (const float*)d_in[4];
    const float* fc  = (const float*)d_in[5];
    const float* fs  = (const float*)d_in[6];
    float* out = (float*)d_out;

    __half *xh, *xl, *wqkvh, *woh, *ath, *atl, *qsh, *qsl, *ksh, *vsh;
    cudaGetSymbolAddress((void**)&xh,    g_xh);     cudaGetSymbolAddress((void**)&xl,  g_xl);
    cudaGetSymbolAddress((void**)&wqkvh, g_wqkv_h);
    cudaGetSymbolAddress((void**)&woh,   g_wot_h);
    cudaGetSymbolAddress((void**)&ath,   g_atth);   cudaGetSymbolAddress((void**)&atl, g_attl);
    cudaGetSymbolAddress((void**)&qsh,   g_qsh);    cudaGetSymbolAddress((void**)&qsl, g_qsl);
    cudaGetSymbolAddress((void**)&ksh,   g_ksh);    cudaGetSymbolAddress((void**)&vsh, g_vsh);

    cudaFuncSetAttribute(gemm_mma_kernel, cudaFuncAttributeMaxDynamicSharedMemorySize, GEMM_SMEM);
    cudaFuncSetAttribute(gemm_qkv_kernel, cudaFuncAttributeMaxDynamicSharedMemorySize, GEMM_SMEM);
    cudaFuncSetAttribute(flash_mma_kernel, cudaFuncAttributeMaxDynamicSharedMemorySize, FLASH_SMEM);

    const int M = BATCH * SEQ;  // 4096

    // weight transposes (hi only) into combined [6144,4096] and wot
    transpose_h_kernel<<<dim3(DMODEL / 32, DMODEL / 32), 256>>>(w_q, wqkvh, DMODEL, DMODEL);
    transpose_h_kernel<<<dim3(NKV / 32, DMODEL / 32), 256>>>(
        w_k, wqkvh + (size_t)DMODEL * DMODEL, DMODEL, NKV);
    transpose_h_kernel<<<dim3(NKV / 32, DMODEL / 32), 256>>>(
        w_v, wqkvh + (size_t)(DMODEL + NKV) * DMODEL, DMODEL, NKV);
    transpose_h_kernel<<<dim3(DMODEL / 32, DMODEL / 32), 256>>>(w_o, woh, DMODEL, DMODEL);

    // x split (hi + lo)
    {
        int n4 = (M * DMODEL) / 4;
        convert_split_kernel<<<(n4 + 255) / 256, 256>>>(x, xh, xl, n4);
    }

    // fused QKV projection + rope + split (one GEMM over N=6144)
    gemm_qkv_kernel<<<dim3(NQKV / 128, M / 128), 256, GEMM_SMEM>>>(
        xh, xl, wqkvh, fc, fs, qsh, qsl, ksh, vsh, DMODEL);

    // flash attention (3 CTAs/SM, heavy tiles first)
    flash_mma_kernel<<<dim3(SEQ / 64, NQH, BATCH), 128, FLASH_SMEM>>>(
        qsh, qsl, ksh, vsh, ath, atl);

    // O projection
    gemm_mma_kernel<<<dim3(DMODEL / 128, M / 128), 256, GEMM_SMEM>>>(
        ath, atl, woh, out, M, DMODEL, DMODEL);
}

// round 14
// speedup vs baseline: 1.0005x; 1.0005x over previous
#include <cuda_runtime.h>
#include <cuda_fp16.h>
#include <math.h>
#include <stdint.h>

#define BATCH 2
#define SEQ 2048
#define DMODEL 4096
#define NQH 32
#define NKVH 8
#define HDIM 128
#define NKV (NKVH * HDIM)        // 1024
#define NQKV (DMODEL + 2 * NKV)  // 6144

// ---------------- scratch (device globals; allocation-free) ----------------
__device__ __half g_xh[(size_t)BATCH * SEQ * DMODEL];
__device__ __half g_xl[(size_t)BATCH * SEQ * DMODEL];
__device__ __half g_wqkv_h[(size_t)NQKV * DMODEL];   // [6144,4096] rows: q,k,v (hi only)
__device__ __half g_wot_h[(size_t)DMODEL * DMODEL];
__device__ __half g_atth[(size_t)BATCH * SEQ * DMODEL];
__device__ __half g_attl[(size_t)BATCH * SEQ * DMODEL];

__device__ __half g_qsh[(size_t)BATCH * SEQ * NQH * HDIM];
__device__ __half g_qsl[(size_t)BATCH * SEQ * NQH * HDIM];
__device__ __half g_ksh[(size_t)BATCH * SEQ * NKV];   // hi only
__device__ __half g_vsh[(size_t)BATCH * SEQ * NKV];   // hi only

__device__ __forceinline__ uint32_t smem_to_u32(const void* p) {
    uint32_t a;
    asm("{ .reg .u64 t; cvta.to.shared.u64 t, %1; cvt.u32.u64 %0, t; }"
        : "=r"(a) : "l"(p));
    return a;
}

#define CP_ASYNC_16(dst, src) \
    asm volatile("cp.async.cg.shared.global [%0], [%1], 16;" :: "r"(dst), "l"(src) : "memory")
#define CP_COMMIT() asm volatile("cp.async.commit_group;" ::: "memory")
#define CP_WAIT_0()  asm volatile("cp.async.wait_group 0;" ::: "memory")
#define CP_WAIT_1()  asm volatile("cp.async.wait_group 1;" ::: "memory")

#define LDMATRIX_X4(r0, r1, r2, r3, addr) \
    asm volatile("ldmatrix.sync.aligned.m8n8.x4.shared.b16 {%0,%1,%2,%3}, [%4];" \
        : "=r"(r0), "=r"(r1), "=r"(r2), "=r"(r3) : "r"(addr))
#define LDMATRIX_X4_T(r0, r1, r2, r3, addr) \
    asm volatile("ldmatrix.sync.aligned.m8n8.x4.trans.shared.b16 {%0,%1,%2,%3}, [%4];" \
        : "=r"(r0), "=r"(r1), "=r"(r2), "=r"(r3) : "r"(addr))

#define MMA_F16(d, a, b0, b1) \
    asm("mma.sync.aligned.m16n8k16.row.col.f32.f16.f16.f32 " \
        "{%0,%1,%2,%3}, {%4,%5,%6,%7}, {%8,%9}, {%0,%1,%2,%3};" \
        : "+f"((d)[0]), "+f"((d)[1]), "+f"((d)[2]), "+f"((d)[3]) \
        : "r"((a)[0]), "r"((a)[1]), "r"((a)[2]), "r"((a)[3]), "r"(b0), "r"(b1))

__device__ __forceinline__ uint32_t pack2h(float a, float b) {
    __half2 t = __floats2half2_rn(a, b);
    return *reinterpret_cast<uint32_t*>(&t);
}
__device__ __forceinline__ void split_pack_h(float a, float b, uint32_t& h, uint32_t& l) {
    __half ha = __float2half_rn(a), hb = __float2half_rn(b);
    h = pack2h(__half2float(ha), __half2float(hb));
    l = pack2h(a - __half2float(ha), b - __half2float(hb));
}

// ---------------- shared GEMM mainloop (device inline) -----------------------
// TBK=64, 2 stages of 3 tiles (Ah, Al, Bh), pitch 144B; 110.6KB -> 2 CTAs/SM.
// Next stage issued BEFORE the wait (wait_group 1) to shorten the serial window.
#define TBK 64
#define APITCH 144
#define TILE_B (128 * APITCH)          // 18432
#define STAGE_B (3 * TILE_B)           // 55296
#define GEMM_SMEM (2 * STAGE_B)        // 110592

struct GemmCtx {
    float acc[2][8][4];
    int lane, wid, wm, wn, bm, bn;
};

__device__ __forceinline__ void gemm_mainloop(
    GemmCtx& g, char* smem_raw,
    const __half* __restrict__ Ah, const __half* __restrict__ Al,
    const __half* __restrict__ Bh, int K)
{
    const uint32_t sbase = smem_to_u32(smem_raw);
    const int tid = threadIdx.x;
    const int lane = g.lane, wm = g.wm, wn = g.wn, bm = g.bm, bn = g.bn;

    const __half* gsrc[3] = {Ah, Al, Bh};
    const int rbase3[3] = {bm, bm, bn};

    auto issue_stage = [&](int it, int buf) {
        const int k0 = it * TBK;
#pragma unroll
        for (int t = 0; t < 3; t++) {
            const __half* gp = gsrc[t] + (size_t)rbase3[t] * K + k0;
            const uint32_t db = sbase + buf * STAGE_B + t * TILE_B;
#pragma unroll
            for (int i = 0; i < 4; i++) {
                int c = i * 256 + tid;          // 1024 chunks of 16B per tile
                int r = c >> 3, ch = c & 7;
                const void* src = gp + (size_t)r * K + ch * 8;
                uint32_t dst = db + r * APITCH + ch * 16;
                CP_ASYNC_16(dst, src);
            }
        }
        CP_COMMIT();
    };

    const int lrow = (lane & 7) + ((lane >> 3) & 1) * 8;
    const int lk   = (lane >> 4) * 8;
    const int nrow = (lane >> 4) * 8 + (lane & 7);
    const int kadd = ((lane >> 3) & 1) * 8;

    // frag loader for one k16 quarter (A hi+lo, B hi)
    auto load_q = [&](uint32_t base, int kk,
                      uint32_t a_h[2][4], uint32_t a_l[2][4], uint32_t b_h[8][2]) {
#pragma unroll
        for (int p = 0; p < 4; p++) {
            uint32_t ab = base + 2 * TILE_B +
                          (wn * 64 + p * 16 + nrow) * APITCH + (kk * 16 + kadd) * 2;
            LDMATRIX_X4(b_h[2*p][0], b_h[2*p][1], b_h[2*p+1][0], b_h[2*p+1][1], ab);
        }
#pragma unroll
        for (int mt = 0; mt < 2; mt++) {
            uint32_t aa = base + (wm * 32 + mt * 16 + lrow) * APITCH +
                          (kk * 16 + lk) * 2;
            LDMATRIX_X4(a_h[mt][0], a_h[mt][1], a_h[mt][2], a_h[mt][3], aa);
            LDMATRIX_X4(a_l[mt][0], a_l[mt][1], a_l[mt][2], a_l[mt][3],
                        aa + TILE_B);
        }
    };

#pragma unroll
    for (int mt = 0; mt < 2; mt++)
#pragma unroll
        for (int nt = 0; nt < 8; nt++)
#pragma unroll
            for (int j = 0; j < 4; j++) g.acc[mt][nt][j] = 0.f;

    const int NITER = K / TBK;   // 64
    issue_stage(0, 0);

    for (int it = 0; it < NITER; it++) {
        // issue next stage BEFORE waiting; buffer (it+1)&1 was released by the
        // trailing barrier of iteration it-1.
        if (it + 1 < NITER) {
            issue_stage(it + 1, (it + 1) & 1);
            CP_WAIT_1();                // stage it resident (newest may fly)
        } else {
            CP_WAIT_0();
        }
        __syncthreads();
        const uint32_t base = sbase + (it & 1) * STAGE_B;

        uint32_t ah[2][2][4], al[2][2][4], bh[2][8][2];
        load_q(base, 0, ah[0], al[0], bh[0]);
#pragma unroll
        for (int kk = 0; kk < 4; kk++) {
            const int cur = kk & 1, nxt = cur ^ 1;
            if (kk < 3) load_q(base, kk + 1, ah[nxt], al[nxt], bh[nxt]);
            // term-major: pass 1 Ah*Bh, pass 2 Al*Bh
#pragma unroll
            for (int mt = 0; mt < 2; mt++)
#pragma unroll
                for (int nt = 0; nt < 8; nt++)
                    MMA_F16(g.acc[mt][nt], ah[cur][mt], bh[cur][nt][0], bh[cur][nt][1]);
#pragma unroll
            for (int mt = 0; mt < 2; mt++)
#pragma unroll
                for (int nt = 0; nt < 8; nt++)
                    MMA_F16(g.acc[mt][nt], al[cur][mt], bh[cur][nt][0], bh[cur][nt][1]);
        }
        __syncthreads();   // release this buffer for the it+2 issue
    }
}

// ---------------- GEMM -> fp32 C (O projection) ------------------------------
__global__ __launch_bounds__(256, 2) void gemm_mma_kernel(
    const __half* __restrict__ Ah, const __half* __restrict__ Al,
    const __half* __restrict__ Bh, float* __restrict__ C, int M, int N, int K)
{
    extern __shared__ __align__(128) char smem_raw[];
    GemmCtx g;
    g.lane = threadIdx.x & 31; g.wid = threadIdx.x >> 5;
    g.wm = g.wid & 3; g.wn = g.wid >> 2;
    g.bm = blockIdx.y * 128; g.bn = blockIdx.x * 128;
    gemm_mainloop(g, smem_raw, Ah, Al, Bh, K);

    const int gr = g.lane >> 2, t2 = (g.lane & 3) * 2;
#pragma unroll
    for (int mt = 0; mt < 2; mt++) {
#pragma unroll
        for (int nt = 0; nt < 8; nt++) {
            int row = g.bm + g.wm * 32 + mt * 16 + gr;
            int col = g.bn + g.wn * 64 + nt * 8 + t2;
            *(float2*)&C[(size_t)row * N + col] =
                make_float2(g.acc[mt][nt][0], g.acc[mt][nt][1]);
            *(float2*)&C[(size_t)(row + 8) * N + col] =
                make_float2(g.acc[mt][nt][2], g.acc[mt][nt][3]);
        }
    }
}

// ---------------- fused QKV GEMM: rope/scale/split epilogue ------------------
__device__ __forceinline__ void rope_split_store_h(
    __half* oh, __half* ol,
    const float* __restrict__ fc, const float* __restrict__ fs,
    int row, int col, float v0, float v1, int stride, int coloff, float scale,
    bool want_lo)
{
    int s = row & (SEQ - 1);
    int i = (col & 127) >> 1;
    float c  = __ldg(fc + s * 64 + i);
    float sn = __ldg(fs + s * 64 + i);
    float ra = (v0 * c - v1 * sn) * scale;
    float rb = (v0 * sn + v1 * c) * scale;
    uint32_t h, l;
    split_pack_h(ra, rb, h, l);
    size_t o = (size_t)row * stride + (col - coloff);
    *(uint32_t*)(oh + o) = h;
    if (want_lo) *(uint32_t*)(ol + o) = l;
}

__global__ __launch_bounds__(256, 2) void gemm_qkv_kernel(
    const __half* __restrict__ Ah, const __half* __restrict__ Al,
    const __half* __restrict__ Bh,
    const float* __restrict__ fc, const float* __restrict__ fs,
    __half* __restrict__ qh, __half* __restrict__ ql,
    __half* __restrict__ kh, __half* __restrict__ vh, int K)
{
    extern __shared__ __align__(128) char smem_raw[];
    GemmCtx g;
    g.lane = threadIdx.x & 31; g.wid = threadIdx.x >> 5;
    g.wm = g.wid & 3; g.wn = g.wid >> 2;
    g.bm = blockIdx.y * 128; g.bn = blockIdx.x * 128;
    gemm_mainloop(g, smem_raw, Ah, Al, Bh, K);

    const int gr = g.lane >> 2, t2 = (g.lane & 3) * 2;
    const float qscale = 0.0883883476483184f;  // 1/sqrt(128)

    if (g.bn < DMODEL) {            // Q: rope + scale + split (hi+lo)
#pragma unroll
        for (int mt = 0; mt < 2; mt++)
#pragma unroll
            for (int nt = 0; nt < 8; nt++) {
                int row = g.bm + g.wm * 32 + mt * 16 + gr;
                int col = g.bn + g.wn * 64 + nt * 8 + t2;
                rope_split_store_h(qh, ql, fc, fs, row, col,
                                   g.acc[mt][nt][0], g.acc[mt][nt][1], DMODEL, 0,
                                   qscale, true);
                rope_split_store_h(qh, ql, fc, fs, row + 8, col,
                                   g.acc[mt][nt][2], g.acc[mt][nt][3], DMODEL, 0,
                                   qscale, true);
            }
    } else if (g.bn < DMODEL + NKV) {  // K: rope, hi only
#pragma unroll
        for (int mt = 0; mt < 2; mt++)
#pragma unroll
            for (int nt = 0; nt < 8; nt++) {
                int row = g.bm + g.wm * 32 + mt * 16 + gr;
                int col = g.bn + g.wn * 64 + nt * 8 + t2;
                rope_split_store_h(kh, nullptr, fc, fs, row, col,
                                   g.acc[mt][nt][0], g.acc[mt][nt][1], NKV, DMODEL,
                                   1.0f, false);
                rope_split_store_h(kh, nullptr, fc, fs, row + 8, col,
                                   g.acc[mt][nt][2], g.acc[mt][nt][3], NKV, DMODEL,
                                   1.0f, false);
            }
    } else {                            // V: hi only
#pragma unroll
        for (int mt = 0; mt < 2; mt++)
#pragma unroll
            for (int nt = 0; nt < 8; nt++) {
                int row = g.bm + g.wm * 32 + mt * 16 + gr;
                int col = g.bn + g.wn * 64 + nt * 8 + t2 - (DMODEL + NKV);
                size_t o0 = (size_t)row * NKV + col;
                *(uint32_t*)(vh + o0) = pack2h(g.acc[mt][nt][0], g.acc[mt][nt][1]);
                size_t o1 = o0 + (size_t)8 * NKV;
                *(uint32_t*)(vh + o1) = pack2h(g.acc[mt][nt][2], g.acc[mt][nt][3]);
            }
    }
}

// ---------------- fp32 -> fp16 hi/lo split (x) --------------------------------
__global__ __launch_bounds__(256) void convert_split_kernel(
    const float* __restrict__ in, __half* __restrict__ oh,
    __half* __restrict__ ol, int n4)
{
    int i = blockIdx.x * blockDim.x + threadIdx.x;
    if (i >= n4) return;
    float4 v = ((const float4*)in)[i];
    uint32_t h0, l0, h1, l1;
    split_pack_h(v.x, v.y, h0, l0);
    split_pack_h(v.z, v.w, h1, l1);
    ((uint2*)oh)[i] = make_uint2(h0, h1);
    ((uint2*)ol)[i] = make_uint2(l0, l1);
}

// ---------------- fp32 [K,N] -> transposed fp16 [N,K] (hi only) --------------
__global__ __launch_bounds__(256) void transpose_h_kernel(
    const float* __restrict__ in, __half* __restrict__ oh, int K, int N)
{
    __shared__ float tile[32][33];
    const int k0 = blockIdx.y * 32, n0 = blockIdx.x * 32;
    const int tx = threadIdx.x & 31, ty = threadIdx.x >> 5;
#pragma unroll
    for (int i = 0; i < 32; i += 8)
        tile[ty + i][tx] = in[(size_t)(k0 + ty + i) * N + n0 + tx];
    __syncthreads();
#pragma unroll
    for (int i = 0; i < 32; i += 8) {
        float v = tile[tx][ty + i];
        oh[(size_t)(n0 + ty + i) * K + k0 + tx] = __float2half_rn(v);
    }
}

// ---------------- flash attention via mma.sync (fp16, A-side split) ----------
// BM=64, 4 warps x 16 rows, 2 CTAs/SM. Q hi+lo; K,V hi only.
// K/V loads via cp.async double buffering; heavy causal tiles launch first.
#define FP 272
#define FQH 0
#define FQL 17408
#define FKV0 34816            // buf0: K at +0, V at +17408
#define KVBUF_B 34816         // one K+V buffer
#define FLASH_SMEM 104448     // Q(2) + 2 x (K+V)

__global__ __launch_bounds__(128, 2) void flash_mma_kernel(
    const __half* __restrict__ Qh, const __half* __restrict__ Ql,
    const __half* __restrict__ Kh, const __half* __restrict__ Vh,
    __half* __restrict__ Oh, __half* __restrict__ Ol)
{
    extern __shared__ __align__(128) char sm[];
    const uint32_t sb = smem_to_u32(sm);
    const int qt = gridDim.x - 1 - blockIdx.x;   // heavy tiles first
    const int h = blockIdx.y, b = blockIdx.z;
    const int kvh = h >> 2;
    const int tid = threadIdx.x, lane = tid & 31, w = tid >> 5;
    const int q0 = qt * 64;

    const int lrow = (lane & 7) + ((lane >> 3) & 1) * 8;
    const int lk   = (lane >> 4) * 8;
    const int nrow = (lane >> 4) * 8 + (lane & 7);
    const int kadd = ((lane >> 3) & 1) * 8;
    const int trow = lane & 15;
    const int tcol = (lane >> 4) * 8;

    // cp.async K+V tile issue into buffer `buf`.
    // Token row stride is NKV halfs (off already includes kvh*HDIM).
    auto issue_kv = [&](int kt, int buf) {
        const size_t off = ((size_t)(b * SEQ + kt * 64) * NKVH + kvh) * HDIM;
        const __half* gk = Kh + off;
        const __half* gv = Vh + off;
        const uint32_t kb = sb + FKV0 + buf * KVBUF_B;
#pragma unroll
        for (int i = 0; i < 8; i++) {
            int c = i * 128 + tid;          // 1024 chunks per tile
            int r = c >> 4, ch = c & 15;
            uint32_t d = r * FP + ch * 16;
            CP_ASYNC_16(kb + d,         gk + (size_t)r * NKV + ch * 8);
            CP_ASYNC_16(kb + 17408 + d, gv + (size_t)r * NKV + ch * 8);
        }
        CP_COMMIT();
    };

    // Q hi/lo tile load (plain, one-time)
    {
        const size_t qoff = ((size_t)(b * SEQ + q0) * NQH + h) * HDIM;
        const uint4* gh = (const uint4*)(Qh + qoff);
        const uint4* gl = (const uint4*)(Ql + qoff);
        for (int i = tid; i < 1024; i += 128) {
            int r = i >> 4, c = i & 15;
            *(uint4*)(sm + FQH + r * FP + c * 16) = gh[(size_t)r * 512 + c];
            *(uint4*)(sm + FQL + r * FP + c * 16) = gl[(size_t)r * 512 + c];
        }
    }

    float m0 = -1e30f, m1 = -1e30f, l0 = 0.f, l1 = 0.f;
    float oacc[16][4];
#pragma unroll
    for (int nt = 0; nt < 16; nt++)
#pragma unroll
        for (int j = 0; j < 4; j++) oacc[nt][j] = 0.f;

    const int row0 = q0 + w * 16 + (lane >> 2);
    const int cb   = 2 * (lane & 3);
    const int ktiles = qt + 1;

    issue_kv(0, 0);

    for (int kt = 0; kt < ktiles; kt++) {
        if (kt + 1 < ktiles) issue_kv(kt + 1, (kt + 1) & 1);
        else CP_COMMIT();               // empty group keeps wait_1 semantics
        CP_WAIT_1();                    // tile kt resident
        __syncthreads();
        const uint32_t FKHb = FKV0 + (kt & 1) * KVBUF_B;
        const uint32_t FVHb = FKHb + 17408;

        float s[8][4];
#pragma unroll
        for (int nt = 0; nt < 8; nt++)
#pragma unroll
            for (int j = 0; j < 4; j++) s[nt][j] = 0.f;

#pragma unroll
        for (int ks = 0; ks < 8; ks++) {
            uint32_t ah[4], al[4];
            uint32_t aa = sb + FQH + (w * 16 + lrow) * FP + (ks * 16 + lk) * 2;
            LDMATRIX_X4(ah[0], ah[1], ah[2], ah[3], aa);
            LDMATRIX_X4(al[0], al[1], al[2], al[3], aa + (FQL - FQH));
            uint32_t bh[8][2];
#pragma unroll
            for (int p = 0; p < 4; p++) {
                uint32_t ba = sb + FKHb + (p * 16 + nrow) * FP + (ks * 16 + kadd) * 2;
                LDMATRIX_X4(bh[2*p][0], bh[2*p][1], bh[2*p+1][0], bh[2*p+1][1], ba);
            }
#pragma unroll
            for (int nt = 0; nt < 8; nt++) MMA_F16(s[nt], ah, bh[nt][0], bh[nt][1]);
#pragma unroll
            for (int nt = 0; nt < 8; nt++) MMA_F16(s[nt], al, bh[nt][0], bh[nt][1]);
        }

        if (kt == qt) {
            const int colb = kt * 64 + cb;
#pragma unroll
            for (int nt = 0; nt < 8; nt++) {
                int c0 = colb + 8 * nt;
                if (c0 > row0)     s[nt][0] = -1e30f;
                if (c0 + 1 > row0) s[nt][1] = -1e30f;
                if (c0 > row0 + 8)     s[nt][2] = -1e30f;
                if (c0 + 1 > row0 + 8) s[nt][3] = -1e30f;
            }
        }

        float mt0 = -1e30f, mt1 = -1e30f;
#pragma unroll
        for (int nt = 0; nt < 8; nt++) {
            mt0 = fmaxf(mt0, fmaxf(s[nt][0], s[nt][1]));
            mt1 = fmaxf(mt1, fmaxf(s[nt][2], s[nt][3]));
        }
        mt0 = fmaxf(mt0, __shfl_xor_sync(0xffffffffu, mt0, 1));
        mt0 = fmaxf(mt0, __shfl_xor_sync(0xffffffffu, mt0, 2));
        mt1 = fmaxf(mt1, __shfl_xor_sync(0xffffffffu, mt1, 1));
        mt1 = fmaxf(mt1, __shfl_xor_sync(0xffffffffu, mt1, 2));
        float mn0 = fmaxf(m0, mt0), mn1 = fmaxf(m1, mt1);
        float a0 = __expf(m0 - mn0), a1 = __expf(m1 - mn1);
        float ps0 = 0.f, ps1 = 0.f;
#pragma unroll
        for (int nt = 0; nt < 8; nt++) {
            s[nt][0] = __expf(s[nt][0] - mn0);
            s[nt][1] = __expf(s[nt][1] - mn0);
            s[nt][2] = __expf(s[nt][2] - mn1);
            s[nt][3] = __expf(s[nt][3] - mn1);
            ps0 += s[nt][0] + s[nt][1];
            ps1 += s[nt][2] + s[nt][3];
        }
        ps0 += __shfl_xor_sync(0xffffffffu, ps0, 1);
        ps0 += __shfl_xor_sync(0xffffffffu, ps0, 2);
        ps1 += __shfl_xor_sync(0xffffffffu, ps1, 1);
        ps1 += __shfl_xor_sync(0xffffffffu, ps1, 2);
        l0 = l0 * a0 + ps0;  m0 = mn0;
        l1 = l1 * a1 + ps1;  m1 = mn1;
#pragma unroll
        for (int nt = 0; nt < 16; nt++) {
            oacc[nt][0] *= a0; oacc[nt][1] *= a0;
            oacc[nt][2] *= a1; oacc[nt][3] *= a1;
        }

        // O += Ph*Vh + Pl*Vh (P residual corrected; V hi only)
#pragma unroll
        for (int j = 0; j < 4; j++) {
            uint32_t ph[4], pl[4];
            split_pack_h(s[2*j][0],   s[2*j][1],   ph[0], pl[0]);
            split_pack_h(s[2*j][2],   s[2*j][3],   ph[1], pl[1]);
            split_pack_h(s[2*j+1][0], s[2*j+1][1], ph[2], pl[2]);
            split_pack_h(s[2*j+1][2], s[2*j+1][3], ph[3], pl[3]);
            uint32_t vfh[8][4];
#pragma unroll
            for (int t = 0; t < 8; t++) {
                uint32_t va = sb + FVHb + (j * 16 + trow) * FP + (t * 16 + tcol) * 2;
                LDMATRIX_X4_T(vfh[t][0], vfh[t][1], vfh[t][2], vfh[t][3], va);
            }
#pragma unroll
            for (int t = 0; t < 8; t++) {
                MMA_F16(oacc[2*t],   ph, vfh[t][0], vfh[t][1]);
                MMA_F16(oacc[2*t+1], ph, vfh[t][2], vfh[t][3]);
            }
#pragma unroll
            for (int t = 0; t < 8; t++) {
                MMA_F16(oacc[2*t],   pl, vfh[t][0], vfh[t][1]);
                MMA_F16(oacc[2*t+1], pl, vfh[t][2], vfh[t][3]);
            }
        }
        __syncthreads();   // all smem reads of this buffer done before reuse
    }

    const float inv0 = 1.f / l0, inv1 = 1.f / l1;
    const size_t o0 = ((size_t)(b * SEQ + row0)) * DMODEL + h * HDIM + cb;
    const size_t o1 = ((size_t)(b * SEQ + row0 + 8)) * DMODEL + h * HDIM + cb;
#pragma unroll
    for (int nt = 0; nt < 16; nt++) {
        uint32_t hh, ll;
        split_pack_h(oacc[nt][0] * inv0, oacc[nt][1] * inv0, hh, ll);
        *(uint32_t*)(Oh + o0 + 8 * nt) = hh;
        *(uint32_t*)(Ol + o0 + 8 * nt) = ll;
        split_pack_h(oacc[nt][2] * inv1, oacc[nt][3] * inv1, hh, ll);
        *(uint32_t*)(Oh + o1 + 8 * nt) = hh;
        *(uint32_t*)(Ol + o1 + 8 * nt) = ll;
    }
}

// ---------------- host launcher ---------------------------------------------
extern "C" void kernel_launch(void* const* d_in, const int* in_sizes, int n_in,
                              void* d_out, int out_size)
{
    const float* x   = (const float*)d_in[0];
    const float* w_q = (const float*)d_in[1];
    const float* w_k = (const float*)d_in[2];
    const float* w_v = (const float*)d_in[3];
    const float* w_o = (const float*)d_in[4];
    const float* fc  = (const float*)d_in[5];
    const float* fs  = (const float*)d_in[6];
    float* out = (float*)d_out;

    __half *xh, *xl, *wqkvh, *woh, *ath, *atl, *qsh, *qsl, *ksh, *vsh;
    cudaGetSymbolAddress((void**)&xh,    g_xh);     cudaGetSymbolAddress((void**)&xl,  g_xl);
    cudaGetSymbolAddress((void**)&wqkvh, g_wqkv_h);
    cudaGetSymbolAddress((void**)&woh,   g_wot_h);
    cudaGetSymbolAddress((void**)&ath,   g_atth);   cudaGetSymbolAddress((void**)&atl, g_attl);
    cudaGetSymbolAddress((void**)&qsh,   g_qsh);    cudaGetSymbolAddress((void**)&qsl, g_qsl);
    cudaGetSymbolAddress((void**)&ksh,   g_ksh);    cudaGetSymbolAddress((void**)&vsh, g_vsh);

    cudaFuncSetAttribute(gemm_mma_kernel, cudaFuncAttributeMaxDynamicSharedMemorySize, GEMM_SMEM);
    cudaFuncSetAttribute(gemm_qkv_kernel, cudaFuncAttributeMaxDynamicSharedMemorySize, GEMM_SMEM);
    cudaFuncSetAttribute(flash_mma_kernel, cudaFuncAttributeMaxDynamicSharedMemorySize, FLASH_SMEM);

    const int M = BATCH * SEQ;  // 4096

    // weight transposes (hi only) into combined [6144,4096] and wot
    transpose_h_kernel<<<dim3(DMODEL / 32, DMODEL / 32), 256>>>(w_q, wqkvh, DMODEL, DMODEL);
    transpose_h_kernel<<<dim3(NKV / 32, DMODEL / 32), 256>>>(
        w_k, wqkvh + (size_t)DMODEL * DMODEL, DMODEL, NKV);
    transpose_h_kernel<<<dim3(NKV / 32, DMODEL / 32), 256>>>(
        w_v, wqkvh + (size_t)(DMODEL + NKV) * DMODEL, DMODEL, NKV);
    transpose_h_kernel<<<dim3(DMODEL / 32, DMODEL / 32), 256>>>(w_o, woh, DMODEL, DMODEL);

    // x split (hi + lo)
    {
        int n4 = (M * DMODEL) / 4;
        convert_split_kernel<<<(n4 + 255) / 256, 256>>>(x, xh, xl, n4);
    }

    // fused QKV projection + rope + split (one GEMM over N=6144)
    gemm_qkv_kernel<<<dim3(NQKV / 128, M / 128), 256, GEMM_SMEM>>>(
        xh, xl, wqkvh, fc, fs, qsh, qsl, ksh, vsh, DMODEL);

    // flash attention (cp.async K/V pipeline, 2 CTAs/SM, heavy tiles first)
    flash_mma_kernel<<<dim3(SEQ / 64, NQH, BATCH), 128, FLASH_SMEM>>>(
        qsh, qsl, ksh, vsh, ath, atl);

    // O projection
    gemm_mma_kernel<<<dim3(DMODEL / 128, M / 128), 256, GEMM_SMEM>>>(
        ath, atl, woh, out, M, DMODEL, DMODEL);
}

// round 15
// speedup vs baseline: 1.0029x; 1.0024x over previous
#include <cuda_runtime.h>
#include <cuda_fp16.h>
#include <math.h>
#include <stdint.h>

#define BATCH 2
#define SEQ 2048
#define DMODEL 4096
#define NQH 32
#define NKVH 8
#define HDIM 128
#define NKV (NKVH * HDIM)        // 1024
#define NQKV (DMODEL + 2 * NKV)  // 6144

// ---------------- scratch (device globals; allocation-free) ----------------
__device__ __half g_xh[(size_t)BATCH * SEQ * DMODEL];
__device__ __half g_xl[(size_t)BATCH * SEQ * DMODEL];
__device__ __half g_wqkv_h[(size_t)NQKV * DMODEL];   // [6144,4096] rows: q,k,v (hi only)
__device__ __half g_wot_h[(size_t)DMODEL * DMODEL];
__device__ __half g_atth[(size_t)BATCH * SEQ * DMODEL];
__device__ __half g_attl[(size_t)BATCH * SEQ * DMODEL];

__device__ __half g_qsh[(size_t)BATCH * SEQ * NQH * HDIM];
__device__ __half g_qsl[(size_t)BATCH * SEQ * NQH * HDIM];
__device__ __half g_ksh[(size_t)BATCH * SEQ * NKV];   // hi only
__device__ __half g_vsh[(size_t)BATCH * SEQ * NKV];   // hi only

__device__ __forceinline__ uint32_t smem_to_u32(const void* p) {
    uint32_t a;
    asm("{ .reg .u64 t; cvta.to.shared.u64 t, %1; cvt.u32.u64 %0, t; }"
        : "=r"(a) : "l"(p));
    return a;
}

#define CP_ASYNC_16(dst, src) \
    asm volatile("cp.async.cg.shared.global [%0], [%1], 16;" :: "r"(dst), "l"(src) : "memory")
#define CP_COMMIT() asm volatile("cp.async.commit_group;" ::: "memory")
#define CP_WAIT_0()  asm volatile("cp.async.wait_group 0;" ::: "memory")
#define CP_WAIT_1()  asm volatile("cp.async.wait_group 1;" ::: "memory")

#define LDMATRIX_X4(r0, r1, r2, r3, addr) \
    asm volatile("ldmatrix.sync.aligned.m8n8.x4.shared.b16 {%0,%1,%2,%3}, [%4];" \
        : "=r"(r0), "=r"(r1), "=r"(r2), "=r"(r3) : "r"(addr))
#define LDMATRIX_X4_T(r0, r1, r2, r3, addr) \
    asm volatile("ldmatrix.sync.aligned.m8n8.x4.trans.shared.b16 {%0,%1,%2,%3}, [%4];" \
        : "=r"(r0), "=r"(r1), "=r"(r2), "=r"(r3) : "r"(addr))

#define MMA_F16(d, a, b0, b1) \
    asm("mma.sync.aligned.m16n8k16.row.col.f32.f16.f16.f32 " \
        "{%0,%1,%2,%3}, {%4,%5,%6,%7}, {%8,%9}, {%0,%1,%2,%3};" \
        : "+f"((d)[0]), "+f"((d)[1]), "+f"((d)[2]), "+f"((d)[3]) \
        : "r"((a)[0]), "r"((a)[1]), "r"((a)[2]), "r"((a)[3]), "r"(b0), "r"(b1))

__device__ __forceinline__ uint32_t pack2h(float a, float b) {
    __half2 t = __floats2half2_rn(a, b);
    return *reinterpret_cast<uint32_t*>(&t);
}
__device__ __forceinline__ void split_pack_h(float a, float b, uint32_t& h, uint32_t& l) {
    __half ha = __float2half_rn(a), hb = __float2half_rn(b);
    h = pack2h(__half2float(ha), __half2float(hb));
    l = pack2h(a - __half2float(ha), b - __half2float(hb));
}

// ---------------- shared GEMM mainloop (device inline) -----------------------
// TBK=64, 2 stages of 3 tiles (Ah, Al, Bh), pitch 144B; 110.6KB -> 2 CTAs/SM.
// R12 ordering: wait -> sync -> issue next -> compute (confirmed optimum).
#define TBK 64
#define APITCH 144
#define TILE_B (128 * APITCH)          // 18432
#define STAGE_B (3 * TILE_B)           // 55296
#define GEMM_SMEM (2 * STAGE_B)        // 110592

struct GemmCtx {
    float acc[2][8][4];
    int lane, wid, wm, wn, bm, bn;
};

__device__ __forceinline__ void gemm_mainloop(
    GemmCtx& g, char* smem_raw,
    const __half* __restrict__ Ah, const __half* __restrict__ Al,
    const __half* __restrict__ Bh, int K)
{
    const uint32_t sbase = smem_to_u32(smem_raw);
    const int tid = threadIdx.x;
    const int lane = g.lane, wm = g.wm, wn = g.wn, bm = g.bm, bn = g.bn;

    const __half* gsrc[3] = {Ah, Al, Bh};
    const int rbase3[3] = {bm, bm, bn};

    auto issue_stage = [&](int it, int buf) {
        const int k0 = it * TBK;
#pragma unroll
        for (int t = 0; t < 3; t++) {
            const __half* gp = gsrc[t] + (size_t)rbase3[t] * K + k0;
            const uint32_t db = sbase + buf * STAGE_B + t * TILE_B;
#pragma unroll
            for (int i = 0; i < 4; i++) {
                int c = i * 256 + tid;          // 1024 chunks of 16B per tile
                int r = c >> 3, ch = c & 7;
                const void* src = gp + (size_t)r * K + ch * 8;
                uint32_t dst = db + r * APITCH + ch * 16;
                CP_ASYNC_16(dst, src);
            }
        }
        CP_COMMIT();
    };

    const int lrow = (lane & 7) + ((lane >> 3) & 1) * 8;
    const int lk   = (lane >> 4) * 8;
    const int nrow = (lane >> 4) * 8 + (lane & 7);
    const int kadd = ((lane >> 3) & 1) * 8;

    // frag loader for one k16 quarter (A hi+lo, B hi)
    auto load_q = [&](uint32_t base, int kk,
                      uint32_t a_h[2][4], uint32_t a_l[2][4], uint32_t b_h[8][2]) {
#pragma unroll
        for (int p = 0; p < 4; p++) {
            uint32_t ab = base + 2 * TILE_B +
                          (wn * 64 + p * 16 + nrow) * APITCH + (kk * 16 + kadd) * 2;
            LDMATRIX_X4(b_h[2*p][0], b_h[2*p][1], b_h[2*p+1][0], b_h[2*p+1][1], ab);
        }
#pragma unroll
        for (int mt = 0; mt < 2; mt++) {
            uint32_t aa = base + (wm * 32 + mt * 16 + lrow) * APITCH +
                          (kk * 16 + lk) * 2;
            LDMATRIX_X4(a_h[mt][0], a_h[mt][1], a_h[mt][2], a_h[mt][3], aa);
            LDMATRIX_X4(a_l[mt][0], a_l[mt][1], a_l[mt][2], a_l[mt][3],
                        aa + TILE_B);
        }
    };

#pragma unroll
    for (int mt = 0; mt < 2; mt++)
#pragma unroll
        for (int nt = 0; nt < 8; nt++)
#pragma unroll
            for (int j = 0; j < 4; j++) g.acc[mt][nt][j] = 0.f;

    const int NITER = K / TBK;   // 64
    issue_stage(0, 0);

    for (int it = 0; it < NITER; it++) {
        CP_WAIT_0();
        __syncthreads();
        if (it + 1 < NITER) issue_stage(it + 1, (it + 1) & 1);
        const uint32_t base = sbase + (it & 1) * STAGE_B;

        uint32_t ah[2][2][4], al[2][2][4], bh[2][8][2];
        load_q(base, 0, ah[0], al[0], bh[0]);
#pragma unroll
        for (int kk = 0; kk < 4; kk++) {
            const int cur = kk & 1, nxt = cur ^ 1;
            if (kk < 3) load_q(base, kk + 1, ah[nxt], al[nxt], bh[nxt]);
            // term-major: pass 1 Ah*Bh, pass 2 Al*Bh
#pragma unroll
            for (int mt = 0; mt < 2; mt++)
#pragma unroll
                for (int nt = 0; nt < 8; nt++)
                    MMA_F16(g.acc[mt][nt], ah[cur][mt], bh[cur][nt][0], bh[cur][nt][1]);
#pragma unroll
            for (int mt = 0; mt < 2; mt++)
#pragma unroll
                for (int nt = 0; nt < 8; nt++)
                    MMA_F16(g.acc[mt][nt], al[cur][mt], bh[cur][nt][0], bh[cur][nt][1]);
        }
        __syncthreads();   // protect stage buffer before next overwrite
    }
}

// ---------------- GEMM -> fp32 C (O projection) ------------------------------
__global__ __launch_bounds__(256, 2) void gemm_mma_kernel(
    const __half* __restrict__ Ah, const __half* __restrict__ Al,
    const __half* __restrict__ Bh, float* __restrict__ C, int M, int N, int K)
{
    extern __shared__ __align__(128) char smem_raw[];
    GemmCtx g;
    g.lane = threadIdx.x & 31; g.wid = threadIdx.x >> 5;
    g.wm = g.wid & 3; g.wn = g.wid >> 2;
    g.bm = blockIdx.y * 128; g.bn = blockIdx.x * 128;
    gemm_mainloop(g, smem_raw, Ah, Al, Bh, K);

    const int gr = g.lane >> 2, t2 = (g.lane & 3) * 2;
#pragma unroll
    for (int mt = 0; mt < 2; mt++) {
#pragma unroll
        for (int nt = 0; nt < 8; nt++) {
            int row = g.bm + g.wm * 32 + mt * 16 + gr;
            int col = g.bn + g.wn * 64 + nt * 8 + t2;
            *(float2*)&C[(size_t)row * N + col] =
                make_float2(g.acc[mt][nt][0], g.acc[mt][nt][1]);
            *(float2*)&C[(size_t)(row + 8) * N + col] =
                make_float2(g.acc[mt][nt][2], g.acc[mt][nt][3]);
        }
    }
}

// ---------------- fused QKV GEMM: rope/scale/split epilogue ------------------
__device__ __forceinline__ void rope_split_store_h(
    __half* oh, __half* ol,
    const float* __restrict__ fc, const float* __restrict__ fs,
    int row, int col, float v0, float v1, int stride, int coloff, float scale,
    bool want_lo)
{
    int s = row & (SEQ - 1);
    int i = (col & 127) >> 1;
    float c  = __ldg(fc + s * 64 + i);
    float sn = __ldg(fs + s * 64 + i);
    float ra = (v0 * c - v1 * sn) * scale;
    float rb = (v0 * sn + v1 * c) * scale;
    uint32_t h, l;
    split_pack_h(ra, rb, h, l);
    size_t o = (size_t)row * stride + (col - coloff);
    *(uint32_t*)(oh + o) = h;
    if (want_lo) *(uint32_t*)(ol + o) = l;
}

__global__ __launch_bounds__(256, 2) void gemm_qkv_kernel(
    const __half* __restrict__ Ah, const __half* __restrict__ Al,
    const __half* __restrict__ Bh,
    const float* __restrict__ fc, const float* __restrict__ fs,
    __half* __restrict__ qh, __half* __restrict__ ql,
    __half* __restrict__ kh, __half* __restrict__ vh, int K)
{
    extern __shared__ __align__(128) char smem_raw[];
    GemmCtx g;
    g.lane = threadIdx.x & 31; g.wid = threadIdx.x >> 5;
    g.wm = g.wid & 3; g.wn = g.wid >> 2;
    g.bm = blockIdx.y * 128; g.bn = blockIdx.x * 128;
    gemm_mainloop(g, smem_raw, Ah, Al, Bh, K);

    const int gr = g.lane >> 2, t2 = (g.lane & 3) * 2;
    const float qscale = 0.0883883476483184f;  // 1/sqrt(128)

    if (g.bn < DMODEL) {            // Q: rope + scale + split (hi+lo)
#pragma unroll
        for (int mt = 0; mt < 2; mt++)
#pragma unroll
            for (int nt = 0; nt < 8; nt++) {
                int row = g.bm + g.wm * 32 + mt * 16 + gr;
                int col = g.bn + g.wn * 64 + nt * 8 + t2;
                rope_split_store_h(qh, ql, fc, fs, row, col,
                                   g.acc[mt][nt][0], g.acc[mt][nt][1], DMODEL, 0,
                                   qscale, true);
                rope_split_store_h(qh, ql, fc, fs, row + 8, col,
                                   g.acc[mt][nt][2], g.acc[mt][nt][3], DMODEL, 0,
                                   qscale, true);
            }
    } else if (g.bn < DMODEL + NKV) {  // K: rope, hi only
#pragma unroll
        for (int mt = 0; mt < 2; mt++)
#pragma unroll
            for (int nt = 0; nt < 8; nt++) {
                int row = g.bm + g.wm * 32 + mt * 16 + gr;
                int col = g.bn + g.wn * 64 + nt * 8 + t2;
                rope_split_store_h(kh, nullptr, fc, fs, row, col,
                                   g.acc[mt][nt][0], g.acc[mt][nt][1], NKV, DMODEL,
                                   1.0f, false);
                rope_split_store_h(kh, nullptr, fc, fs, row + 8, col,
                                   g.acc[mt][nt][2], g.acc[mt][nt][3], NKV, DMODEL,
                                   1.0f, false);
            }
    } else {                            // V: hi only
#pragma unroll
        for (int mt = 0; mt < 2; mt++)
#pragma unroll
            for (int nt = 0; nt < 8; nt++) {
                int row = g.bm + g.wm * 32 + mt * 16 + gr;
                int col = g.bn + g.wn * 64 + nt * 8 + t2 - (DMODEL + NKV);
                size_t o0 = (size_t)row * NKV + col;
                *(uint32_t*)(vh + o0) = pack2h(g.acc[mt][nt][0], g.acc[mt][nt][1]);
                size_t o1 = o0 + (size_t)8 * NKV;
                *(uint32_t*)(vh + o1) = pack2h(g.acc[mt][nt][2], g.acc[mt][nt][3]);
            }
    }
}

// ---------------- fp32 -> fp16 hi/lo split (x) --------------------------------
__global__ __launch_bounds__(256) void convert_split_kernel(
    const float* __restrict__ in, __half* __restrict__ oh,
    __half* __restrict__ ol, int n4)
{
    int i = blockIdx.x * blockDim.x + threadIdx.x;
    if (i >= n4) return;
    float4 v = ((const float4*)in)[i];
    uint32_t h0, l0, h1, l1;
    split_pack_h(v.x, v.y, h0, l0);
    split_pack_h(v.z, v.w, h1, l1);
    ((uint2*)oh)[i] = make_uint2(h0, h1);
    ((uint2*)ol)[i] = make_uint2(l0, l1);
}

// ---------------- fp32 [K,N] -> transposed fp16 [N,K] (hi only) --------------
// 64-wide k tiles, 512 threads; stores are __half2 -> 128B per warp.
__global__ __launch_bounds__(512) void transpose_h_kernel(
    const float* __restrict__ in, __half* __restrict__ oh, int K, int N)
{
    __shared__ float tile[64][33];
    const int k0 = blockIdx.y * 64, n0 = blockIdx.x * 32;
    const int tx = threadIdx.x & 31, ty = threadIdx.x >> 5;   // 32 x 16
    // load: rows = k (64), cols = n (32); each thread 4 rows
#pragma unroll
    for (int i = 0; i < 64; i += 16)
        tile[ty + i][tx] = in[(size_t)(k0 + ty + i) * N + n0 + tx];
    __syncthreads();
    // store: each thread writes __half2 covering k = 2*tx, 2*tx+1 for row n0+ty+i
#pragma unroll
    for (int i = 0; i < 32; i += 16) {
        float v0 = tile[2 * tx][ty + i];      // in[k0+2tx][n0+ty+i]
        float v1 = tile[2 * tx + 1][ty + i];
        *(uint32_t*)(oh + (size_t)(n0 + ty + i) * K + k0 + 2 * tx) = pack2h(v0, v1);
    }
}

// ---------------- flash attention via mma.sync (fp16, A-side split) ----------
// BM=64, 4 warps x 16 rows, 2 CTAs/SM. Q hi+lo; K,V hi only.
// K/V loads via cp.async double buffering; heavy causal tiles launch first.
#define FP 272
#define FQH 0
#define FQL 17408
#define FKV0 34816            // buf0: K at +0, V at +17408
#define KVBUF_B 34816         // one K+V buffer
#define FLASH_SMEM 104448     // Q(2) + 2 x (K+V)

__global__ __launch_bounds__(128, 2) void flash_mma_kernel(
    const __half* __restrict__ Qh, const __half* __restrict__ Ql,
    const __half* __restrict__ Kh, const __half* __restrict__ Vh,
    __half* __restrict__ Oh, __half* __restrict__ Ol)
{
    extern __shared__ __align__(128) char sm[];
    const uint32_t sb = smem_to_u32(sm);
    const int qt = gridDim.x - 1 - blockIdx.x;   // heavy tiles first
    const int h = blockIdx.y, b = blockIdx.z;
    const int kvh = h >> 2;
    const int tid = threadIdx.x, lane = tid & 31, w = tid >> 5;
    const int q0 = qt * 64;

    const int lrow = (lane & 7) + ((lane >> 3) & 1) * 8;
    const int lk   = (lane >> 4) * 8;
    const int nrow = (lane >> 4) * 8 + (lane & 7);
    const int kadd = ((lane >> 3) & 1) * 8;
    const int trow = lane & 15;
    const int tcol = (lane >> 4) * 8;

    auto issue_kv = [&](int kt, int buf) {
        const size_t off = ((size_t)(b * SEQ + kt * 64) * NKVH + kvh) * HDIM;
        const __half* gk = Kh + off;
        const __half* gv = Vh + off;
        const uint32_t kb = sb + FKV0 + buf * KVBUF_B;
#pragma unroll
        for (int i = 0; i < 8; i++) {
            int c = i * 128 + tid;
            int r = c >> 4, ch = c & 15;
            uint32_t d = r * FP + ch * 16;
            CP_ASYNC_16(kb + d,         gk + (size_t)r * NKV + ch * 8);
            CP_ASYNC_16(kb + 17408 + d, gv + (size_t)r * NKV + ch * 8);
        }
        CP_COMMIT();
    };

    {
        const size_t qoff = ((size_t)(b * SEQ + q0) * NQH + h) * HDIM;
        const uint4* gh = (const uint4*)(Qh + qoff);
        const uint4* gl = (const uint4*)(Ql + qoff);
        for (int i = tid; i < 1024; i += 128) {
            int r = i >> 4, c = i & 15;
            *(uint4*)(sm + FQH + r * FP + c * 16) = gh[(size_t)r * 512 + c];
            *(uint4*)(sm + FQL + r * FP + c * 16) = gl[(size_t)r * 512 + c];
        }
    }

    float m0 = -1e30f, m1 = -1e30f, l0 = 0.f, l1 = 0.f;
    float oacc[16][4];
#pragma unroll
    for (int nt = 0; nt < 16; nt++)
#pragma unroll
        for (int j = 0; j < 4; j++) oacc[nt][j] = 0.f;

    const int row0 = q0 + w * 16 + (lane >> 2);
    const int cb   = 2 * (lane & 3);
    const int ktiles = qt + 1;

    issue_kv(0, 0);

    for (int kt = 0; kt < ktiles; kt++) {
        if (kt + 1 < ktiles) issue_kv(kt + 1, (kt + 1) & 1);
        else CP_COMMIT();
        CP_WAIT_1();
        __syncthreads();
        const uint32_t FKHb = FKV0 + (kt & 1) * KVBUF_B;
        const uint32_t FVHb = FKHb + 17408;

        float s[8][4];
#pragma unroll
        for (int nt = 0; nt < 8; nt++)
#pragma unroll
            for (int j = 0; j < 4; j++) s[nt][j] = 0.f;

#pragma unroll
        for (int ks = 0; ks < 8; ks++) {
            uint32_t ah[4], al[4];
            uint32_t aa = sb + FQH + (w * 16 + lrow) * FP + (ks * 16 + lk) * 2;
            LDMATRIX_X4(ah[0], ah[1], ah[2], ah[3], aa);
            LDMATRIX_X4(al[0], al[1], al[2], al[3], aa + (FQL - FQH));
            uint32_t bh[8][2];
#pragma unroll
            for (int p = 0; p < 4; p++) {
                uint32_t ba = sb + FKHb + (p * 16 + nrow) * FP + (ks * 16 + kadd) * 2;
                LDMATRIX_X4(bh[2*p][0], bh[2*p][1], bh[2*p+1][0], bh[2*p+1][1], ba);
            }
#pragma unroll
            for (int nt = 0; nt < 8; nt++) MMA_F16(s[nt], ah, bh[nt][0], bh[nt][1]);
#pragma unroll
            for (int nt = 0; nt < 8; nt++) MMA_F16(s[nt], al, bh[nt][0], bh[nt][1]);
        }

        if (kt == qt) {
            const int colb = kt * 64 + cb;
#pragma unroll
            for (int nt = 0; nt < 8; nt++) {
                int c0 = colb + 8 * nt;
                if (c0 > row0)     s[nt][0] = -1e30f;
                if (c0 + 1 > row0) s[nt][1] = -1e30f;
                if (c0 > row0 + 8)     s[nt][2] = -1e30f;
                if (c0 + 1 > row0 + 8) s[nt][3] = -1e30f;
            }
        }

        float mt0 = -1e30f, mt1 = -1e30f;
#pragma unroll
        for (int nt = 0; nt < 8; nt++) {
            mt0 = fmaxf(mt0, fmaxf(s[nt][0], s[nt][1]));
            mt1 = fmaxf(mt1, fmaxf(s[nt][2], s[nt][3]));
        }
        mt0 = fmaxf(mt0, __shfl_xor_sync(0xffffffffu, mt0, 1));
        mt0 = fmaxf(mt0, __shfl_xor_sync(0xffffffffu, mt0, 2));
        mt1 = fmaxf(mt1, __shfl_xor_sync(0xffffffffu, mt1, 1));
        mt1 = fmaxf(mt1, __shfl_xor_sync(0xffffffffu, mt1, 2));
        float mn0 = fmaxf(m0, mt0), mn1 = fmaxf(m1, mt1);
        float a0 = __expf(m0 - mn0), a1 = __expf(m1 - mn1);
        float ps0 = 0.f, ps1 = 0.f;
#pragma unroll
        for (int nt = 0; nt < 8; nt++) {
            s[nt][0] = __expf(s[nt][0] - mn0);
            s[nt][1] = __expf(s[nt][1] - mn0);
            s[nt][2] = __expf(s[nt][2] - mn1);
            s[nt][3] = __expf(s[nt][3] - mn1);
            ps0 += s[nt][0] + s[nt][1];
            ps1 += s[nt][2] + s[nt][3];
        }
        ps0 += __shfl_xor_sync(0xffffffffu, ps0, 1);
        ps0 += __shfl_xor_sync(0xffffffffu, ps0, 2);
        ps1 += __shfl_xor_sync(0xffffffffu, ps1, 1);
        ps1 += __shfl_xor_sync(0xffffffffu, ps1, 2);
        l0 = l0 * a0 + ps0;  m0 = mn0;
        l1 = l1 * a1 + ps1;  m1 = mn1;
#pragma unroll
        for (int nt = 0; nt < 16; nt++) {
            oacc[nt][0] *= a0; oacc[nt][1] *= a0;
            oacc[nt][2] *= a1; oacc[nt][3] *= a1;
        }

        // O += Ph*Vh + Pl*Vh
#pragma unroll
        for (int j = 0; j < 4; j++) {
            uint32_t ph[4], pl[4];
            split_pack_h(s[2*j][0],   s[2*j][1],   ph[0], pl[0]);
            split_pack_h(s[2*j][2],   s[2*j][3],   ph[1], pl[1]);
            split_pack_h(s[2*j+1][0], s[2*j+1][1], ph[2], pl[2]);
            split_pack_h(s[2*j+1][2], s[2*j+1][3], ph[3], pl[3]);
            uint32_t vfh[8][4];
#pragma unroll
            for (int t = 0; t < 8; t++) {
                uint32_t va = sb + FVHb + (j * 16 + trow) * FP + (t * 16 + tcol) * 2;
                LDMATRIX_X4_T(vfh[t][0], vfh[t][1], vfh[t][2], vfh[t][3], va);
            }
#pragma unroll
            for (int t = 0; t < 8; t++) {
                MMA_F16(oacc[2*t],   ph, vfh[t][0], vfh[t][1]);
                MMA_F16(oacc[2*t+1], ph, vfh[t][2], vfh[t][3]);
            }
#pragma unroll
            for (int t = 0; t < 8; t++) {
                MMA_F16(oacc[2*t],   pl, vfh[t][0], vfh[t][1]);
                MMA_F16(oacc[2*t+1], pl, vfh[t][2], vfh[t][3]);
            }
        }
        __syncthreads();
    }

    const float inv0 = 1.f / l0, inv1 = 1.f / l1;
    const size_t o0 = ((size_t)(b * SEQ + row0)) * DMODEL + h * HDIM + cb;
    const size_t o1 = ((size_t)(b * SEQ + row0 + 8)) * DMODEL + h * HDIM + cb;
#pragma unroll
    for (int nt = 0; nt < 16; nt++) {
        uint32_t hh, ll;
        split_pack_h(oacc[nt][0] * inv0, oacc[nt][1] * inv0, hh, ll);
        *(uint32_t*)(Oh + o0 + 8 * nt) = hh;
        *(uint32_t*)(Ol + o0 + 8 * nt) = ll;
        split_pack_h(oacc[nt][2] * inv1, oacc[nt][3] * inv1, hh, ll);
        *(uint32_t*)(Oh + o1 + 8 * nt) = hh;
        *(uint32_t*)(Ol + o1 + 8 * nt) = ll;
    }
}

// ---------------- host launcher ---------------------------------------------
extern "C" void kernel_launch(void* const* d_in, const int* in_sizes, int n_in,
                              void* d_out, int out_size)
{
    const float* x   = (const float*)d_in[0];
    const float* w_q = (const float*)d_in[1];
    const float* w_k = (const float*)d_in[2];
    const float* w_v = (const float*)d_in[3];
    const float* w_o = (const float*)d_in[4];
    const float* fc  = (const float*)d_in[5];
    const float* fs  = (const float*)d_in[6];
    float* out = (float*)d_out;

    __half *xh, *xl, *wqkvh, *woh, *ath, *atl, *qsh, *qsl, *ksh, *vsh;
    cudaGetSymbolAddress((void**)&xh,    g_xh);     cudaGetSymbolAddress((void**)&xl,  g_xl);
    cudaGetSymbolAddress((void**)&wqkvh, g_wqkv_h);
    cudaGetSymbolAddress((void**)&woh,   g_wot_h);
    cudaGetSymbolAddress((void**)&ath,   g_atth);   cudaGetSymbolAddress((void**)&atl, g_attl);
    cudaGetSymbolAddress((void**)&qsh,   g_qsh);    cudaGetSymbolAddress((void**)&qsl, g_qsl);
    cudaGetSymbolAddress((void**)&ksh,   g_ksh);    cudaGetSymbolAddress((void**)&vsh, g_vsh);

    cudaFuncSetAttribute(gemm_mma_kernel, cudaFuncAttributeMaxDynamicSharedMemorySize, GEMM_SMEM);
    cudaFuncSetAttribute(gemm_qkv_kernel, cudaFuncAttributeMaxDynamicSharedMemorySize, GEMM_SMEM);
    cudaFuncSetAttribute(flash_mma_kernel, cudaFuncAttributeMaxDynamicSharedMemorySize, FLASH_SMEM);

    const int M = BATCH * SEQ;  // 4096

    // weight transposes (hi only); 64-wide k tiles, half2 stores
    transpose_h_kernel<<<dim3(DMODEL / 32, DMODEL / 64), 512>>>(w_q, wqkvh, DMODEL, DMODEL);
    transpose_h_kernel<<<dim3(NKV / 32, DMODEL / 64), 512>>>(
        w_k, wqkvh + (size_t)DMODEL * DMODEL, DMODEL, NKV);
    transpose_h_kernel<<<dim3(NKV / 32, DMODEL / 64), 512>>>(
        w_v, wqkvh + (size_t)(DMODEL + NKV) * DMODEL, DMODEL, NKV);
    transpose_h_kernel<<<dim3(DMODEL / 32, DMODEL / 64), 512>>>(w_o, woh, DMODEL, DMODEL);

    // x split (hi + lo)
    {
        int n4 = (M * DMODEL) / 4;
        convert_split_kernel<<<(n4 + 255) / 256, 256>>>(x, xh, xl, n4);
    }

    // fused QKV projection + rope + split (one GEMM over N=6144)
    gemm_qkv_kernel<<<dim3(NQKV / 128, M / 128), 256, GEMM_SMEM>>>(
        xh, xl, wqkvh, fc, fs, qsh, qsl, ksh, vsh, DMODEL);

    // flash attention (cp.async K/V pipeline, 2 CTAs/SM, heavy tiles first)
    flash_mma_kernel<<<dim3(SEQ / 64, NQH, BATCH), 128, FLASH_SMEM>>>(
        qsh, qsl, ksh, vsh, ath, atl);

    // O projection
    gemm_mma_kernel<<<dim3(DMODEL / 128, M / 128), 256, GEMM_SMEM>>>(
        ath, atl, woh, out, M, DMODEL, DMODEL);
}

// round 16
// speedup vs baseline: 1.0077x; 1.0048x over previous
#include <cuda_runtime.h>
#include <cuda_fp16.h>
#include <math.h>
#include <stdint.h>

#define BATCH 2
#define SEQ 2048
#define DMODEL 4096
#define NQH 32
#define NKVH 8
#define HDIM 128
#define NKV (NKVH * HDIM)        // 1024
#define NQKV (DMODEL + 2 * NKV)  // 6144

// ---------------- scratch (device globals; allocation-free) ----------------
__device__ __half g_xh[(size_t)BATCH * SEQ * DMODEL];
__device__ __half g_xl[(size_t)BATCH * SEQ * DMODEL];
__device__ __half g_wqkv_h[(size_t)NQKV * DMODEL];   // [6144,4096] rows: q,k,v (hi only)
__device__ __half g_wot_h[(size_t)DMODEL * DMODEL];
__device__ __half g_atth[(size_t)BATCH * SEQ * DMODEL];
__device__ __half g_attl[(size_t)BATCH * SEQ * DMODEL];

__device__ __half g_qsh[(size_t)BATCH * SEQ * NQH * HDIM];
__device__ __half g_qsl[(size_t)BATCH * SEQ * NQH * HDIM];
__device__ __half g_ksh[(size_t)BATCH * SEQ * NKV];   // hi only
__device__ __half g_vsh[(size_t)BATCH * SEQ * NKV];   // hi only

__device__ __forceinline__ uint32_t smem_to_u32(const void* p) {
    uint32_t a;
    asm("{ .reg .u64 t; cvta.to.shared.u64 t, %1; cvt.u32.u64 %0, t; }"
        : "=r"(a) : "l"(p));
    return a;
}

#define CP_ASYNC_16(dst, src) \
    asm volatile("cp.async.cg.shared.global [%0], [%1], 16;" :: "r"(dst), "l"(src) : "memory")
#define CP_COMMIT() asm volatile("cp.async.commit_group;" ::: "memory")
#define CP_WAIT_0()  asm volatile("cp.async.wait_group 0;" ::: "memory")
#define CP_WAIT_1()  asm volatile("cp.async.wait_group 1;" ::: "memory")

#define LDMATRIX_X4(r0, r1, r2, r3, addr) \
    asm volatile("ldmatrix.sync.aligned.m8n8.x4.shared.b16 {%0,%1,%2,%3}, [%4];" \
        : "=r"(r0), "=r"(r1), "=r"(r2), "=r"(r3) : "r"(addr))
#define LDMATRIX_X4_T(r0, r1, r2, r3, addr) \
    asm volatile("ldmatrix.sync.aligned.m8n8.x4.trans.shared.b16 {%0,%1,%2,%3}, [%4];" \
        : "=r"(r0), "=r"(r1), "=r"(r2), "=r"(r3) : "r"(addr))

#define MMA_F16(d, a, b0, b1) \
    asm("mma.sync.aligned.m16n8k16.row.col.f32.f16.f16.f32 " \
        "{%0,%1,%2,%3}, {%4,%5,%6,%7}, {%8,%9}, {%0,%1,%2,%3};" \
        : "+f"((d)[0]), "+f"((d)[1]), "+f"((d)[2]), "+f"((d)[3]) \
        : "r"((a)[0]), "r"((a)[1]), "r"((a)[2]), "r"((a)[3]), "r"(b0), "r"(b1))

__device__ __forceinline__ uint32_t pack2h(float a, float b) {
    __half2 t = __floats2half2_rn(a, b);
    return *reinterpret_cast<uint32_t*>(&t);
}
__device__ __forceinline__ void split_pack_h(float a, float b, uint32_t& h, uint32_t& l) {
    __half ha = __float2half_rn(a), hb = __float2half_rn(b);
    h = pack2h(__half2float(ha), __half2float(hb));
    l = pack2h(a - __half2float(ha), b - __half2float(hb));
}

// ---------------- shared GEMM mainloop (device inline) -----------------------
// TBK=64, 2 stages of 3 tiles (Ah, Al, Bh), pitch 144B; 110.6KB -> 2 CTAs/SM.
// R12 ordering: wait -> sync -> issue next -> compute (confirmed optimum).
#define TBK 64
#define APITCH 144
#define TILE_B (128 * APITCH)          // 18432
#define STAGE_B (3 * TILE_B)           // 55296
#define GEMM_SMEM (2 * STAGE_B)        // 110592

struct GemmCtx {
    float acc[2][8][4];
    int lane, wid, wm, wn, bm, bn;
};

__device__ __forceinline__ void gemm_mainloop(
    GemmCtx& g, char* smem_raw,
    const __half* __restrict__ Ah, const __half* __restrict__ Al,
    const __half* __restrict__ Bh, int K)
{
    const uint32_t sbase = smem_to_u32(smem_raw);
    const int tid = threadIdx.x;
    const int lane = g.lane, wm = g.wm, wn = g.wn, bm = g.bm, bn = g.bn;

    const __half* gsrc[3] = {Ah, Al, Bh};
    const int rbase3[3] = {bm, bm, bn};

    auto issue_stage = [&](int it, int buf) {
        const int k0 = it * TBK;
#pragma unroll
        for (int t = 0; t < 3; t++) {
            const __half* gp = gsrc[t] + (size_t)rbase3[t] * K + k0;
            const uint32_t db = sbase + buf * STAGE_B + t * TILE_B;
#pragma unroll
            for (int i = 0; i < 4; i++) {
                int c = i * 256 + tid;          // 1024 chunks of 16B per tile
                int r = c >> 3, ch = c & 7;
                const void* src = gp + (size_t)r * K + ch * 8;
                uint32_t dst = db + r * APITCH + ch * 16;
                CP_ASYNC_16(dst, src);
            }
        }
        CP_COMMIT();
    };

    const int lrow = (lane & 7) + ((lane >> 3) & 1) * 8;
    const int lk   = (lane >> 4) * 8;
    const int nrow = (lane >> 4) * 8 + (lane & 7);
    const int kadd = ((lane >> 3) & 1) * 8;

    // frag loader for one k16 quarter (A hi+lo, B hi)
    auto load_q = [&](uint32_t base, int kk,
                      uint32_t a_h[2][4], uint32_t a_l[2][4], uint32_t b_h[8][2]) {
#pragma unroll
        for (int p = 0; p < 4; p++) {
            uint32_t ab = base + 2 * TILE_B +
                          (wn * 64 + p * 16 + nrow) * APITCH + (kk * 16 + kadd) * 2;
            LDMATRIX_X4(b_h[2*p][0], b_h[2*p][1], b_h[2*p+1][0], b_h[2*p+1][1], ab);
        }
#pragma unroll
        for (int mt = 0; mt < 2; mt++) {
            uint32_t aa = base + (wm * 32 + mt * 16 + lrow) * APITCH +
                          (kk * 16 + lk) * 2;
            LDMATRIX_X4(a_h[mt][0], a_h[mt][1], a_h[mt][2], a_h[mt][3], aa);
            LDMATRIX_X4(a_l[mt][0], a_l[mt][1], a_l[mt][2], a_l[mt][3],
                        aa + TILE_B);
        }
    };

#pragma unroll
    for (int mt = 0; mt < 2; mt++)
#pragma unroll
        for (int nt = 0; nt < 8; nt++)
#pragma unroll
            for (int j = 0; j < 4; j++) g.acc[mt][nt][j] = 0.f;

    const int NITER = K / TBK;   // 64
    issue_stage(0, 0);

    for (int it = 0; it < NITER; it++) {
        CP_WAIT_0();
        __syncthreads();
        if (it + 1 < NITER) issue_stage(it + 1, (it + 1) & 1);
        const uint32_t base = sbase + (it & 1) * STAGE_B;

        uint32_t ah[2][2][4], al[2][2][4], bh[2][8][2];
        load_q(base, 0, ah[0], al[0], bh[0]);
#pragma unroll
        for (int kk = 0; kk < 4; kk++) {
            const int cur = kk & 1, nxt = cur ^ 1;
            if (kk < 3) load_q(base, kk + 1, ah[nxt], al[nxt], bh[nxt]);
            // term-major: pass 1 Ah*Bh, pass 2 Al*Bh
#pragma unroll
            for (int mt = 0; mt < 2; mt++)
#pragma unroll
                for (int nt = 0; nt < 8; nt++)
                    MMA_F16(g.acc[mt][nt], ah[cur][mt], bh[cur][nt][0], bh[cur][nt][1]);
#pragma unroll
            for (int mt = 0; mt < 2; mt++)
#pragma unroll
                for (int nt = 0; nt < 8; nt++)
                    MMA_F16(g.acc[mt][nt], al[cur][mt], bh[cur][nt][0], bh[cur][nt][1]);
        }
        __syncthreads();   // protect stage buffer before next overwrite
    }
}

// ---------------- GEMM -> fp32 C (O projection) ------------------------------
__global__ __launch_bounds__(256, 2) void gemm_mma_kernel(
    const __half* __restrict__ Ah, const __half* __restrict__ Al,
    const __half* __restrict__ Bh, float* __restrict__ C, int M, int N, int K)
{
    extern __shared__ __align__(128) char smem_raw[];
    GemmCtx g;
    g.lane = threadIdx.x & 31; g.wid = threadIdx.x >> 5;
    g.wm = g.wid & 3; g.wn = g.wid >> 2;
    g.bm = blockIdx.y * 128; g.bn = blockIdx.x * 128;
    gemm_mainloop(g, smem_raw, Ah, Al, Bh, K);

    const int gr = g.lane >> 2, t2 = (g.lane & 3) * 2;
#pragma unroll
    for (int mt = 0; mt < 2; mt++) {
#pragma unroll
        for (int nt = 0; nt < 8; nt++) {
            int row = g.bm + g.wm * 32 + mt * 16 + gr;
            int col = g.bn + g.wn * 64 + nt * 8 + t2;
            *(float2*)&C[(size_t)row * N + col] =
                make_float2(g.acc[mt][nt][0], g.acc[mt][nt][1]);
            *(float2*)&C[(size_t)(row + 8) * N + col] =
                make_float2(g.acc[mt][nt][2], g.acc[mt][nt][3]);
        }
    }
}

// ---------------- fused QKV GEMM: rope/scale/split epilogue ------------------
__device__ __forceinline__ void rope_split_store_h(
    __half* oh, __half* ol,
    const float* __restrict__ fc, const float* __restrict__ fs,
    int row, int col, float v0, float v1, int stride, int coloff, float scale,
    bool want_lo)
{
    int s = row & (SEQ - 1);
    int i = (col & 127) >> 1;
    float c  = __ldg(fc + s * 64 + i);
    float sn = __ldg(fs + s * 64 + i);
    float ra = (v0 * c - v1 * sn) * scale;
    float rb = (v0 * sn + v1 * c) * scale;
    uint32_t h, l;
    split_pack_h(ra, rb, h, l);
    size_t o = (size_t)row * stride + (col - coloff);
    *(uint32_t*)(oh + o) = h;
    if (want_lo) *(uint32_t*)(ol + o) = l;
}

__global__ __launch_bounds__(256, 2) void gemm_qkv_kernel(
    const __half* __restrict__ Ah, const __half* __restrict__ Al,
    const __half* __restrict__ Bh,
    const float* __restrict__ fc, const float* __restrict__ fs,
    __half* __restrict__ qh, __half* __restrict__ ql,
    __half* __restrict__ kh, __half* __restrict__ vh, int K)
{
    extern __shared__ __align__(128) char smem_raw[];
    GemmCtx g;
    g.lane = threadIdx.x & 31; g.wid = threadIdx.x >> 5;
    g.wm = g.wid & 3; g.wn = g.wid >> 2;
    g.bm = blockIdx.y * 128; g.bn = blockIdx.x * 128;
    gemm_mainloop(g, smem_raw, Ah, Al, Bh, K);

    const int gr = g.lane >> 2, t2 = (g.lane & 3) * 2;
    const float qscale = 0.0883883476483184f;  // 1/sqrt(128)

    if (g.bn < DMODEL) {            // Q: rope + scale + split (hi+lo)
#pragma unroll
        for (int mt = 0; mt < 2; mt++)
#pragma unroll
            for (int nt = 0; nt < 8; nt++) {
                int row = g.bm + g.wm * 32 + mt * 16 + gr;
                int col = g.bn + g.wn * 64 + nt * 8 + t2;
                rope_split_store_h(qh, ql, fc, fs, row, col,
                                   g.acc[mt][nt][0], g.acc[mt][nt][1], DMODEL, 0,
                                   qscale, true);
                rope_split_store_h(qh, ql, fc, fs, row + 8, col,
                                   g.acc[mt][nt][2], g.acc[mt][nt][3], DMODEL, 0,
                                   qscale, true);
            }
    } else if (g.bn < DMODEL + NKV) {  // K: rope, hi only
#pragma unroll
        for (int mt = 0; mt < 2; mt++)
#pragma unroll
            for (int nt = 0; nt < 8; nt++) {
                int row = g.bm + g.wm * 32 + mt * 16 + gr;
                int col = g.bn + g.wn * 64 + nt * 8 + t2;
                rope_split_store_h(kh, nullptr, fc, fs, row, col,
                                   g.acc[mt][nt][0], g.acc[mt][nt][1], NKV, DMODEL,
                                   1.0f, false);
                rope_split_store_h(kh, nullptr, fc, fs, row + 8, col,
                                   g.acc[mt][nt][2], g.acc[mt][nt][3], NKV, DMODEL,
                                   1.0f, false);
            }
    } else {                            // V: hi only
#pragma unroll
        for (int mt = 0; mt < 2; mt++)
#pragma unroll
            for (int nt = 0; nt < 8; nt++) {
                int row = g.bm + g.wm * 32 + mt * 16 + gr;
                int col = g.bn + g.wn * 64 + nt * 8 + t2 - (DMODEL + NKV);
                size_t o0 = (size_t)row * NKV + col;
                *(uint32_t*)(vh + o0) = pack2h(g.acc[mt][nt][0], g.acc[mt][nt][1]);
                size_t o1 = o0 + (size_t)8 * NKV;
                *(uint32_t*)(vh + o1) = pack2h(g.acc[mt][nt][2], g.acc[mt][nt][3]);
            }
    }
}

// ---------------- fp32 -> fp16 hi/lo split (x) --------------------------------
__global__ __launch_bounds__(256) void convert_split_kernel(
    const float* __restrict__ in, __half* __restrict__ oh,
    __half* __restrict__ ol, int n4)
{
    int i = blockIdx.x * blockDim.x + threadIdx.x;
    if (i >= n4) return;
    float4 v = ((const float4*)in)[i];
    uint32_t h0, l0, h1, l1;
    split_pack_h(v.x, v.y, h0, l0);
    split_pack_h(v.z, v.w, h1, l1);
    ((uint2*)oh)[i] = make_uint2(h0, h1);
    ((uint2*)ol)[i] = make_uint2(l0, l1);
}

// ---------------- fused weight transpose: all four matrices, one launch ------
// R12's proven 32x33 fp32 tile; linear block-id decode over 4 ranges.
#define WQ_TILES (128 * 128)   // 4096/32 x 4096/32
#define WK_TILES (32 * 128)    // 1024/32 x 4096/32
#define WV_TILES (32 * 128)
#define WO_TILES (128 * 128)

__device__ __forceinline__ void transpose_tile32(
    const float* __restrict__ in, __half* __restrict__ oh,
    int K, int N, int bx, int by)
{
    __shared__ float tile[32][33];
    const int k0 = by * 32, n0 = bx * 32;
    const int tx = threadIdx.x & 31, ty = threadIdx.x >> 5;
#pragma unroll
    for (int i = 0; i < 32; i += 8)
        tile[ty + i][tx] = in[(size_t)(k0 + ty + i) * N + n0 + tx];
    __syncthreads();
#pragma unroll
    for (int i = 0; i < 32; i += 8) {
        float v = tile[tx][ty + i];
        oh[(size_t)(n0 + ty + i) * K + k0 + tx] = __float2half_rn(v);
    }
}

__global__ __launch_bounds__(256) void transpose_all_kernel(
    const float* __restrict__ w_q, const float* __restrict__ w_k,
    const float* __restrict__ w_v, const float* __restrict__ w_o,
    __half* __restrict__ wqkvh, __half* __restrict__ woh)
{
    int bid = blockIdx.x;
    if (bid < WQ_TILES) {
        transpose_tile32(w_q, wqkvh, DMODEL, DMODEL, bid % 128, bid / 128);
    } else if (bid < WQ_TILES + WK_TILES) {
        int r = bid - WQ_TILES;
        transpose_tile32(w_k, wqkvh + (size_t)DMODEL * DMODEL,
                         DMODEL, NKV, r % 32, r / 32);
    } else if (bid < WQ_TILES + WK_TILES + WV_TILES) {
        int r = bid - WQ_TILES - WK_TILES;
        transpose_tile32(w_v, wqkvh + (size_t)(DMODEL + NKV) * DMODEL,
                         DMODEL, NKV, r % 32, r / 32);
    } else {
        int r = bid - WQ_TILES - WK_TILES - WV_TILES;
        transpose_tile32(w_o, woh, DMODEL, DMODEL, r % 128, r / 128);
    }
}

// ---------------- flash attention via mma.sync (fp16, A-side split) ----------
// BM=64, 4 warps x 16 rows, 2 CTAs/SM. Q hi+lo; K,V hi only.
// K/V loads via cp.async double buffering; heavy causal tiles launch first.
#define FP 272
#define FQH 0
#define FQL 17408
#define FKV0 34816            // buf0: K at +0, V at +17408
#define KVBUF_B 34816         // one K+V buffer
#define FLASH_SMEM 104448     // Q(2) + 2 x (K+V)

__global__ __launch_bounds__(128, 2) void flash_mma_kernel(
    const __half* __restrict__ Qh, const __half* __restrict__ Ql,
    const __half* __restrict__ Kh, const __half* __restrict__ Vh,
    __half* __restrict__ Oh, __half* __restrict__ Ol)
{
    extern __shared__ __align__(128) char sm[];
    const uint32_t sb = smem_to_u32(sm);
    const int qt = gridDim.x - 1 - blockIdx.x;   // heavy tiles first
    const int h = blockIdx.y, b = blockIdx.z;
    const int kvh = h >> 2;
    const int tid = threadIdx.x, lane = tid & 31, w = tid >> 5;
    const int q0 = qt * 64;

    const int lrow = (lane & 7) + ((lane >> 3) & 1) * 8;
    const int lk   = (lane >> 4) * 8;
    const int nrow = (lane >> 4) * 8 + (lane & 7);
    const int kadd = ((lane >> 3) & 1) * 8;
    const int trow = lane & 15;
    const int tcol = (lane >> 4) * 8;

    auto issue_kv = [&](int kt, int buf) {
        const size_t off = ((size_t)(b * SEQ + kt * 64) * NKVH + kvh) * HDIM;
        const __half* gk = Kh + off;
        const __half* gv = Vh + off;
        const uint32_t kb = sb + FKV0 + buf * KVBUF_B;
#pragma unroll
        for (int i = 0; i < 8; i++) {
            int c = i * 128 + tid;
            int r = c >> 4, ch = c & 15;
            uint32_t d = r * FP + ch * 16;
            CP_ASYNC_16(kb + d,         gk + (size_t)r * NKV + ch * 8);
            CP_ASYNC_16(kb + 17408 + d, gv + (size_t)r * NKV + ch * 8);
        }
        CP_COMMIT();
    };

    {
        const size_t qoff = ((size_t)(b * SEQ + q0) * NQH + h) * HDIM;
        const uint4* gh = (const uint4*)(Qh + qoff);
        const uint4* gl = (const uint4*)(Ql + qoff);
        for (int i = tid; i < 1024; i += 128) {
            int r = i >> 4, c = i & 15;
            *(uint4*)(sm + FQH + r * FP + c * 16) = gh[(size_t)r * 512 + c];
            *(uint4*)(sm + FQL + r * FP + c * 16) = gl[(size_t)r * 512 + c];
        }
    }

    float m0 = -1e30f, m1 = -1e30f, l0 = 0.f, l1 = 0.f;
    float oacc[16][4];
#pragma unroll
    for (int nt = 0; nt < 16; nt++)
#pragma unroll
        for (int j = 0; j < 4; j++) oacc[nt][j] = 0.f;

    const int row0 = q0 + w * 16 + (lane >> 2);
    const int cb   = 2 * (lane & 3);
    const int ktiles = qt + 1;

    issue_kv(0, 0);

    for (int kt = 0; kt < ktiles; kt++) {
        if (kt + 1 < ktiles) issue_kv(kt + 1, (kt + 1) & 1);
        else CP_COMMIT();
        CP_WAIT_1();
        __syncthreads();
        const uint32_t FKHb = FKV0 + (kt & 1) * KVBUF_B;
        const uint32_t FVHb = FKHb + 17408;

        float s[8][4];
#pragma unroll
        for (int nt = 0; nt < 8; nt++)
#pragma unroll
            for (int j = 0; j < 4; j++) s[nt][j] = 0.f;

#pragma unroll
        for (int ks = 0; ks < 8; ks++) {
            uint32_t ah[4], al[4];
            uint32_t aa = sb + FQH + (w * 16 + lrow) * FP + (ks * 16 + lk) * 2;
            LDMATRIX_X4(ah[0], ah[1], ah[2], ah[3], aa);
            LDMATRIX_X4(al[0], al[1], al[2], al[3], aa + (FQL - FQH));
            uint32_t bh[8][2];
#pragma unroll
            for (int p = 0; p < 4; p++) {
                uint32_t ba = sb + FKHb + (p * 16 + nrow) * FP + (ks * 16 + kadd) * 2;
                LDMATRIX_X4(bh[2*p][0], bh[2*p][1], bh[2*p+1][0], bh[2*p+1][1], ba);
            }
#pragma unroll
            for (int nt = 0; nt < 8; nt++) MMA_F16(s[nt], ah, bh[nt][0], bh[nt][1]);
#pragma unroll
            for (int nt = 0; nt < 8; nt++) MMA_F16(s[nt], al, bh[nt][0], bh[nt][1]);
        }

        if (kt == qt) {
            const int colb = kt * 64 + cb;
#pragma unroll
            for (int nt = 0; nt < 8; nt++) {
                int c0 = colb + 8 * nt;
                if (c0 > row0)     s[nt][0] = -1e30f;
                if (c0 + 1 > row0) s[nt][1] = -1e30f;
                if (c0 > row0 + 8)     s[nt][2] = -1e30f;
                if (c0 + 1 > row0 + 8) s[nt][3] = -1e30f;
            }
        }

        float mt0 = -1e30f, mt1 = -1e30f;
#pragma unroll
        for (int nt = 0; nt < 8; nt++) {
            mt0 = fmaxf(mt0, fmaxf(s[nt][0], s[nt][1]));
            mt1 = fmaxf(mt1, fmaxf(s[nt][2], s[nt][3]));
        }
        mt0 = fmaxf(mt0, __shfl_xor_sync(0xffffffffu, mt0, 1));
        mt0 = fmaxf(mt0, __shfl_xor_sync(0xffffffffu, mt0, 2));
        mt1 = fmaxf(mt1, __shfl_xor_sync(0xffffffffu, mt1, 1));
        mt1 = fmaxf(mt1, __shfl_xor_sync(0xffffffffu, mt1, 2));
        float mn0 = fmaxf(m0, mt0), mn1 = fmaxf(m1, mt1);
        float a0 = __expf(m0 - mn0), a1 = __expf(m1 - mn1);
        float ps0 = 0.f, ps1 = 0.f;
#pragma unroll
        for (int nt = 0; nt < 8; nt++) {
            s[nt][0] = __expf(s[nt][0] - mn0);
            s[nt][1] = __expf(s[nt][1] - mn0);
            s[nt][2] = __expf(s[nt][2] - mn1);
            s[nt][3] = __expf(s[nt][3] - mn1);
            ps0 += s[nt][0] + s[nt][1];
            ps1 += s[nt][2] + s[nt][3];
        }
        ps0 += __shfl_xor_sync(0xffffffffu, ps0, 1);
        ps0 += __shfl_xor_sync(0xffffffffu, ps0, 2);
        ps1 += __shfl_xor_sync(0xffffffffu, ps1, 1);
        ps1 += __shfl_xor_sync(0xffffffffu, ps1, 2);
        l0 = l0 * a0 + ps0;  m0 = mn0;
        l1 = l1 * a1 + ps1;  m1 = mn1;
#pragma unroll
        for (int nt = 0; nt < 16; nt++) {
            oacc[nt][0] *= a0; oacc[nt][1] *= a0;
            oacc[nt][2] *= a1; oacc[nt][3] *= a1;
        }

        // O += Ph*Vh + Pl*Vh
#pragma unroll
        for (int j = 0; j < 4; j++) {
            uint32_t ph[4], pl[4];
            split_pack_h(s[2*j][0],   s[2*j][1],   ph[0], pl[0]);
            split_pack_h(s[2*j][2],   s[2*j][3],   ph[1], pl[1]);
            split_pack_h(s[2*j+1][0], s[2*j+1][1], ph[2], pl[2]);
            split_pack_h(s[2*j+1][2], s[2*j+1][3], ph[3], pl[3]);
            uint32_t vfh[8][4];
#pragma unroll
            for (int t = 0; t < 8; t++) {
                uint32_t va = sb + FVHb + (j * 16 + trow) * FP + (t * 16 + tcol) * 2;
                LDMATRIX_X4_T(vfh[t][0], vfh[t][1], vfh[t][2], vfh[t][3], va);
            }
#pragma unroll
            for (int t = 0; t < 8; t++) {
                MMA_F16(oacc[2*t],   ph, vfh[t][0], vfh[t][1]);
                MMA_F16(oacc[2*t+1], ph, vfh[t][2], vfh[t][3]);
            }
#pragma unroll
            for (int t = 0; t < 8; t++) {
                MMA_F16(oacc[2*t],   pl, vfh[t][0], vfh[t][1]);
                MMA_F16(oacc[2*t+1], pl, vfh[t][2], vfh[t][3]);
            }
        }
        __syncthreads();
    }

    const float inv0 = 1.f / l0, inv1 = 1.f / l1;
    const size_t o0 = ((size_t)(b * SEQ + row0)) * DMODEL + h * HDIM + cb;
    const size_t o1 = ((size_t)(b * SEQ + row0 + 8)) * DMODEL + h * HDIM + cb;
#pragma unroll
    for (int nt = 0; nt < 16; nt++) {
        uint32_t hh, ll;
        split_pack_h(oacc[nt][0] * inv0, oacc[nt][1] * inv0, hh, ll);
        *(uint32_t*)(Oh + o0 + 8 * nt) = hh;
        *(uint32_t*)(Ol + o0 + 8 * nt) = ll;
        split_pack_h(oacc[nt][2] * inv1, oacc[nt][3] * inv1, hh, ll);
        *(uint32_t*)(Oh + o1 + 8 * nt) = hh;
        *(uint32_t*)(Ol + o1 + 8 * nt) = ll;
    }
}

// ---------------- host launcher ---------------------------------------------
extern "C" void kernel_launch(void* const* d_in, const int* in_sizes, int n_in,
                              void* d_out, int out_size)
{
    const float* x   = (const float*)d_in[0];
    const float* w_q = (const float*)d_in[1];
    const float* w_k = (const float*)d_in[2];
    const float* w_v = (const float*)d_in[3];
    const float* w_o = (const float*)d_in[4];
    const float* fc  = (const float*)d_in[5];
    const float* fs  = (const float*)d_in[6];
    float* out = (float*)d_out;

    __half *xh, *xl, *wqkvh, *woh, *ath, *atl, *qsh, *qsl, *ksh, *vsh;
    cudaGetSymbolAddress((void**)&xh,    g_xh);     cudaGetSymbolAddress((void**)&xl,  g_xl);
    cudaGetSymbolAddress((void**)&wqkvh, g_wqkv_h);
    cudaGetSymbolAddress((void**)&woh,   g_wot_h);
    cudaGetSymbolAddress((void**)&ath,   g_atth);   cudaGetSymbolAddress((void**)&atl, g_attl);
    cudaGetSymbolAddress((void**)&qsh,   g_qsh);    cudaGetSymbolAddress((void**)&qsl, g_qsl);
    cudaGetSymbolAddress((void**)&ksh,   g_ksh);    cudaGetSymbolAddress((void**)&vsh, g_vsh);

    cudaFuncSetAttribute(gemm_mma_kernel, cudaFuncAttributeMaxDynamicSharedMemorySize, GEMM_SMEM);
    cudaFuncSetAttribute(gemm_qkv_kernel, cudaFuncAttributeMaxDynamicSharedMemorySize, GEMM_SMEM);
    cudaFuncSetAttribute(flash_mma_kernel, cudaFuncAttributeMaxDynamicSharedMemorySize, FLASH_SMEM);

    const int M = BATCH * SEQ;  // 4096

    // all four weight transposes in one launch
    transpose_all_kernel<<<WQ_TILES + WK_TILES + WV_TILES + WO_TILES, 256>>>(
        w_q, w_k, w_v, w_o, wqkvh, woh);

    // x split (hi + lo)
    {
        int n4 = (M * DMODEL) / 4;
        convert_split_kernel<<<(n4 + 255) / 256, 256>>>(x, xh, xl, n4);
    }

    // fused QKV projection + rope + split (one GEMM over N=6144)
    gemm_qkv_kernel<<<dim3(NQKV / 128, M / 128), 256, GEMM_SMEM>>>(
        xh, xl, wqkvh, fc, fs, qsh, qsl, ksh, vsh, DMODEL);

    // flash attention (cp.async K/V pipeline, 2 CTAs/SM, heavy tiles first)
    flash_mma_kernel<<<dim3(SEQ / 64, NQH, BATCH), 128, FLASH_SMEM>>>(
        qsh, qsl, ksh, vsh, ath, atl);

    // O projection
    gemm_mma_kernel<<<dim3(DMODEL / 128, M / 128), 256, GEMM_SMEM>>>(
        ath, atl, woh, out, M, DMODEL, DMODEL);
}

// round 17
// speedup vs baseline: 1.0405x; 1.0325x over previous
#include <cuda_runtime.h>
#include <cuda_fp16.h>
#include <math.h>
#include <stdint.h>

#define BATCH 2
#define SEQ 2048
#define DMODEL 4096
#define NQH 32
#define NKVH 8
#define HDIM 128
#define NKV (NKVH * HDIM)        // 1024
#define NQKV (DMODEL + 2 * NKV)  // 6144

// ---------------- scratch (device globals; allocation-free) ----------------
__device__ __half g_xh[(size_t)BATCH * SEQ * DMODEL];
__device__ __half g_xl[(size_t)BATCH * SEQ * DMODEL];
__device__ __half g_wqkv_h[(size_t)NQKV * DMODEL];   // [6144,4096] rows: q,k,v (hi only)
__device__ __half g_wot_h[(size_t)DMODEL * DMODEL];
__device__ __half g_atth[(size_t)BATCH * SEQ * DMODEL];
__device__ __half g_attl[(size_t)BATCH * SEQ * DMODEL];

__device__ __half g_qsh[(size_t)BATCH * SEQ * NQH * HDIM];
__device__ __half g_qsl[(size_t)BATCH * SEQ * NQH * HDIM];
__device__ __half g_ksh[(size_t)BATCH * SEQ * NKV];   // hi only
__device__ __half g_vsh[(size_t)BATCH * SEQ * NKV];   // hi only

__device__ __forceinline__ uint32_t smem_to_u32(const void* p) {
    uint32_t a;
    asm("{ .reg .u64 t; cvta.to.shared.u64 t, %1; cvt.u32.u64 %0, t; }"
        : "=r"(a) : "l"(p));
    return a;
}

#define CP_ASYNC_16(dst, src) \
    asm volatile("cp.async.cg.shared.global [%0], [%1], 16;" :: "r"(dst), "l"(src) : "memory")
#define CP_COMMIT() asm volatile("cp.async.commit_group;" ::: "memory")
#define CP_WAIT_0()  asm volatile("cp.async.wait_group 0;" ::: "memory")
#define CP_WAIT_1()  asm volatile("cp.async.wait_group 1;" ::: "memory")

#define LDMATRIX_X4(r0, r1, r2, r3, addr) \
    asm volatile("ldmatrix.sync.aligned.m8n8.x4.shared.b16 {%0,%1,%2,%3}, [%4];" \
        : "=r"(r0), "=r"(r1), "=r"(r2), "=r"(r3) : "r"(addr))
#define LDMATRIX_X4_T(r0, r1, r2, r3, addr) \
    asm volatile("ldmatrix.sync.aligned.m8n8.x4.trans.shared.b16 {%0,%1,%2,%3}, [%4];" \
        : "=r"(r0), "=r"(r1), "=r"(r2), "=r"(r3) : "r"(addr))

#define MMA_F16(d, a, b0, b1) \
    asm("mma.sync.aligned.m16n8k16.row.col.f32.f16.f16.f32 " \
        "{%0,%1,%2,%3}, {%4,%5,%6,%7}, {%8,%9}, {%0,%1,%2,%3};" \
        : "+f"((d)[0]), "+f"((d)[1]), "+f"((d)[2]), "+f"((d)[3]) \
        : "r"((a)[0]), "r"((a)[1]), "r"((a)[2]), "r"((a)[3]), "r"(b0), "r"(b1))

__device__ __forceinline__ uint32_t pack2h(float a, float b) {
    __half2 t = __floats2half2_rn(a, b);
    return *reinterpret_cast<uint32_t*>(&t);
}
__device__ __forceinline__ void split_pack_h(float a, float b, uint32_t& h, uint32_t& l) {
    __half ha = __float2half_rn(a), hb = __float2half_rn(b);
    h = pack2h(__half2float(ha), __half2float(hb));
    l = pack2h(a - __half2float(ha), b - __half2float(hb));
}

// ---------------- shared GEMM mainloop (device inline) -----------------------
// TBK=64, 2 stages of 3 tiles (Ah, Al, Bh), pitch 144B; 110.6KB -> 2 CTAs/SM.
#define TBK 64
#define APITCH 144
#define TILE_B (128 * APITCH)          // 18432
#define STAGE_B (3 * TILE_B)           // 55296
#define GEMM_SMEM (2 * STAGE_B)        // 110592

struct GemmCtx {
    float acc[2][8][4];
    int lane, wid, wm, wn, bm, bn;
};

__device__ __forceinline__ void gemm_mainloop(
    GemmCtx& g, char* smem_raw,
    const __half* __restrict__ Ah, const __half* __restrict__ Al,
    const __half* __restrict__ Bh, int K)
{
    const uint32_t sbase = smem_to_u32(smem_raw);
    const int tid = threadIdx.x;
    const int lane = g.lane, wm = g.wm, wn = g.wn, bm = g.bm, bn = g.bn;

    const __half* gsrc[3] = {Ah, Al, Bh};
    const int rbase3[3] = {bm, bm, bn};

    auto issue_stage = [&](int it, int buf) {
        const int k0 = it * TBK;
#pragma unroll
        for (int t = 0; t < 3; t++) {
            const __half* gp = gsrc[t] + (size_t)rbase3[t] * K + k0;
            const uint32_t db = sbase + buf * STAGE_B + t * TILE_B;
#pragma unroll
            for (int i = 0; i < 4; i++) {
                int c = i * 256 + tid;          // 1024 chunks of 16B per tile
                int r = c >> 3, ch = c & 7;
                const void* src = gp + (size_t)r * K + ch * 8;
                uint32_t dst = db + r * APITCH + ch * 16;
                CP_ASYNC_16(dst, src);
            }
        }
        CP_COMMIT();
    };

    const int lrow = (lane & 7) + ((lane >> 3) & 1) * 8;
    const int lk   = (lane >> 4) * 8;
    const int nrow = (lane >> 4) * 8 + (lane & 7);
    const int kadd = ((lane >> 3) & 1) * 8;

    auto load_q = [&](uint32_t base, int kk,
                      uint32_t a_h[2][4], uint32_t a_l[2][4], uint32_t b_h[8][2]) {
#pragma unroll
        for (int p = 0; p < 4; p++) {
            uint32_t ab = base + 2 * TILE_B +
                          (wn * 64 + p * 16 + nrow) * APITCH + (kk * 16 + kadd) * 2;
            LDMATRIX_X4(b_h[2*p][0], b_h[2*p][1], b_h[2*p+1][0], b_h[2*p+1][1], ab);
        }
#pragma unroll
        for (int mt = 0; mt < 2; mt++) {
            uint32_t aa = base + (wm * 32 + mt * 16 + lrow) * APITCH +
                          (kk * 16 + lk) * 2;
            LDMATRIX_X4(a_h[mt][0], a_h[mt][1], a_h[mt][2], a_h[mt][3], aa);
            LDMATRIX_X4(a_l[mt][0], a_l[mt][1], a_l[mt][2], a_l[mt][3],
                        aa + TILE_B);
        }
    };

#pragma unroll
    for (int mt = 0; mt < 2; mt++)
#pragma unroll
        for (int nt = 0; nt < 8; nt++)
#pragma unroll
            for (int j = 0; j < 4; j++) g.acc[mt][nt][j] = 0.f;

    const int NITER = K / TBK;   // 64
    issue_stage(0, 0);

    for (int it = 0; it < NITER; it++) {
        CP_WAIT_0();
        __syncthreads();
        if (it + 1 < NITER) issue_stage(it + 1, (it + 1) & 1);
        const uint32_t base = sbase + (it & 1) * STAGE_B;

        uint32_t ah[2][2][4], al[2][2][4], bh[2][8][2];
        load_q(base, 0, ah[0], al[0], bh[0]);
#pragma unroll
        for (int kk = 0; kk < 4; kk++) {
            const int cur = kk & 1, nxt = cur ^ 1;
            if (kk < 3) load_q(base, kk + 1, ah[nxt], al[nxt], bh[nxt]);
#pragma unroll
            for (int mt = 0; mt < 2; mt++)
#pragma unroll
                for (int nt = 0; nt < 8; nt++)
                    MMA_F16(g.acc[mt][nt], ah[cur][mt], bh[cur][nt][0], bh[cur][nt][1]);
#pragma unroll
            for (int mt = 0; mt < 2; mt++)
#pragma unroll
                for (int nt = 0; nt < 8; nt++)
                    MMA_F16(g.acc[mt][nt], al[cur][mt], bh[cur][nt][0], bh[cur][nt][1]);
        }
        __syncthreads();
    }
}

// ---------------- GEMM -> fp32 C (O projection) ------------------------------
__global__ __launch_bounds__(256, 2) void gemm_mma_kernel(
    const __half* __restrict__ Ah, const __half* __restrict__ Al,
    const __half* __restrict__ Bh, float* __restrict__ C, int M, int N, int K)
{
    extern __shared__ __align__(128) char smem_raw[];
    GemmCtx g;
    g.lane = threadIdx.x & 31; g.wid = threadIdx.x >> 5;
    g.wm = g.wid & 3; g.wn = g.wid >> 2;
    g.bm = blockIdx.y * 128; g.bn = blockIdx.x * 128;
    gemm_mainloop(g, smem_raw, Ah, Al, Bh, K);

    const int gr = g.lane >> 2, t2 = (g.lane & 3) * 2;
#pragma unroll
    for (int mt = 0; mt < 2; mt++) {
#pragma unroll
        for (int nt = 0; nt < 8; nt++) {
            int row = g.bm + g.wm * 32 + mt * 16 + gr;
            int col = g.bn + g.wn * 64 + nt * 8 + t2;
            *(float2*)&C[(size_t)row * N + col] =
                make_float2(g.acc[mt][nt][0], g.acc[mt][nt][1]);
            *(float2*)&C[(size_t)(row + 8) * N + col] =
                make_float2(g.acc[mt][nt][2], g.acc[mt][nt][3]);
        }
    }
}

// ---------------- fused QKV GEMM: rope/scale/split epilogue ------------------
__device__ __forceinline__ void rope_split_store_h(
    __half* oh, __half* ol,
    const float* __restrict__ fc, const float* __restrict__ fs,
    int row, int col, float v0, float v1, int stride, int coloff, float scale,
    bool want_lo)
{
    int s = row & (SEQ - 1);
    int i = (col & 127) >> 1;
    float c  = __ldg(fc + s * 64 + i);
    float sn = __ldg(fs + s * 64 + i);
    float ra = (v0 * c - v1 * sn) * scale;
    float rb = (v0 * sn + v1 * c) * scale;
    uint32_t h, l;
    split_pack_h(ra, rb, h, l);
    size_t o = (size_t)row * stride + (col - coloff);
    *(uint32_t*)(oh + o) = h;
    if (want_lo) *(uint32_t*)(ol + o) = l;
}

__global__ __launch_bounds__(256, 2) void gemm_qkv_kernel(
    const __half* __restrict__ Ah, const __half* __restrict__ Al,
    const __half* __restrict__ Bh,
    const float* __restrict__ fc, const float* __restrict__ fs,
    __half* __restrict__ qh, __half* __restrict__ ql,
    __half* __restrict__ kh, __half* __restrict__ vh, int K)
{
    extern __shared__ __align__(128) char smem_raw[];
    GemmCtx g;
    g.lane = threadIdx.x & 31; g.wid = threadIdx.x >> 5;
    g.wm = g.wid & 3; g.wn = g.wid >> 2;
    g.bm = blockIdx.y * 128; g.bn = blockIdx.x * 128;
    gemm_mainloop(g, smem_raw, Ah, Al, Bh, K);

    const int gr = g.lane >> 2, t2 = (g.lane & 3) * 2;
    const float qscale = 0.0883883476483184f;  // 1/sqrt(128)

    if (g.bn < DMODEL) {
#pragma unroll
        for (int mt = 0; mt < 2; mt++)
#pragma unroll
            for (int nt = 0; nt < 8; nt++) {
                int row = g.bm + g.wm * 32 + mt * 16 + gr;
                int col = g.bn + g.wn * 64 + nt * 8 + t2;
                rope_split_store_h(qh, ql, fc, fs, row, col,
                                   g.acc[mt][nt][0], g.acc[mt][nt][1], DMODEL, 0,
                                   qscale, true);
                rope_split_store_h(qh, ql, fc, fs, row + 8, col,
                                   g.acc[mt][nt][2], g.acc[mt][nt][3], DMODEL, 0,
                                   qscale, true);
            }
    } else if (g.bn < DMODEL + NKV) {
#pragma unroll
        for (int mt = 0; mt < 2; mt++)
#pragma unroll
            for (int nt = 0; nt < 8; nt++) {
                int row = g.bm + g.wm * 32 + mt * 16 + gr;
                int col = g.bn + g.wn * 64 + nt * 8 + t2;
                rope_split_store_h(kh, nullptr, fc, fs, row, col,
                                   g.acc[mt][nt][0], g.acc[mt][nt][1], NKV, DMODEL,
                                   1.0f, false);
                rope_split_store_h(kh, nullptr, fc, fs, row + 8, col,
                                   g.acc[mt][nt][2], g.acc[mt][nt][3], NKV, DMODEL,
                                   1.0f, false);
            }
    } else {
#pragma unroll
        for (int mt = 0; mt < 2; mt++)
#pragma unroll
            for (int nt = 0; nt < 8; nt++) {
                int row = g.bm + g.wm * 32 + mt * 16 + gr;
                int col = g.bn + g.wn * 64 + nt * 8 + t2 - (DMODEL + NKV);
                size_t o0 = (size_t)row * NKV + col;
                *(uint32_t*)(vh + o0) = pack2h(g.acc[mt][nt][0], g.acc[mt][nt][1]);
                size_t o1 = o0 + (size_t)8 * NKV;
                *(uint32_t*)(vh + o1) = pack2h(g.acc[mt][nt][2], g.acc[mt][nt][3]);
            }
    }
}

// ---------------- fused prep: 4 weight transposes + x split, one launch ------
#define WQ_TILES (128 * 128)
#define WK_TILES (32 * 128)
#define WV_TILES (32 * 128)
#define WO_TILES (128 * 128)
#define N_TRANS (WQ_TILES + WK_TILES + WV_TILES + WO_TILES)   // 40960
#define N_CONV ((BATCH * SEQ * DMODEL / 4) / 256)             // 16384

__device__ __forceinline__ void transpose_tile32(
    const float* __restrict__ in, __half* __restrict__ oh,
    int K, int N, int bx, int by)
{
    __shared__ float tile[32][33];
    const int k0 = by * 32, n0 = bx * 32;
    const int tx = threadIdx.x & 31, ty = threadIdx.x >> 5;
#pragma unroll
    for (int i = 0; i < 32; i += 8)
        tile[ty + i][tx] = in[(size_t)(k0 + ty + i) * N + n0 + tx];
    __syncthreads();
#pragma unroll
    for (int i = 0; i < 32; i += 8) {
        float v = tile[tx][ty + i];
        oh[(size_t)(n0 + ty + i) * K + k0 + tx] = __float2half_rn(v);
    }
}

__global__ __launch_bounds__(256) void prep_kernel(
    const float* __restrict__ w_q, const float* __restrict__ w_k,
    const float* __restrict__ w_v, const float* __restrict__ w_o,
    const float* __restrict__ x,
    __half* __restrict__ wqkvh, __half* __restrict__ woh,
    __half* __restrict__ xh, __half* __restrict__ xl)
{
    int bid = blockIdx.x;
    if (bid < WQ_TILES) {
        transpose_tile32(w_q, wqkvh, DMODEL, DMODEL, bid % 128, bid / 128);
    } else if (bid < WQ_TILES + WK_TILES) {
        int r = bid - WQ_TILES;
        transpose_tile32(w_k, wqkvh + (size_t)DMODEL * DMODEL,
                         DMODEL, NKV, r % 32, r / 32);
    } else if (bid < WQ_TILES + WK_TILES + WV_TILES) {
        int r = bid - WQ_TILES - WK_TILES;
        transpose_tile32(w_v, wqkvh + (size_t)(DMODEL + NKV) * DMODEL,
                         DMODEL, NKV, r % 32, r / 32);
    } else if (bid < N_TRANS) {
        int r = bid - WQ_TILES - WK_TILES - WV_TILES;
        transpose_tile32(w_o, woh, DMODEL, DMODEL, r % 128, r / 128);
    } else {
        int i = (bid - N_TRANS) * 256 + threadIdx.x;
        float4 v = ((const float4*)x)[i];
        uint32_t h0, l0, h1, l1;
        split_pack_h(v.x, v.y, h0, l0);
        split_pack_h(v.z, v.w, h1, l1);
        ((uint2*)xh)[i] = make_uint2(h0, h1);
        ((uint2*)xl)[i] = make_uint2(l0, l1);
    }
}

// ---------------- flash attention via mma.sync (fp16) ------------------------
// BM=64, 4 warps x 16 rows, 2 CTAs/SM. Q hi+lo; K,V hi; P hi only (Pl dropped).
// K/V loads via cp.async double buffering; heavy causal tiles launch first.
#define FP 272
#define FQH 0
#define FQL 17408
#define FKV0 34816
#define KVBUF_B 34816
#define FLASH_SMEM 104448

__global__ __launch_bounds__(128, 2) void flash_mma_kernel(
    const __half* __restrict__ Qh, const __half* __restrict__ Ql,
    const __half* __restrict__ Kh, const __half* __restrict__ Vh,
    __half* __restrict__ Oh, __half* __restrict__ Ol)
{
    extern __shared__ __align__(128) char sm[];
    const uint32_t sb = smem_to_u32(sm);
    const int qt = gridDim.x - 1 - blockIdx.x;
    const int h = blockIdx.y, b = blockIdx.z;
    const int kvh = h >> 2;
    const int tid = threadIdx.x, lane = tid & 31, w = tid >> 5;
    const int q0 = qt * 64;

    const int lrow = (lane & 7) + ((lane >> 3) & 1) * 8;
    const int lk   = (lane >> 4) * 8;
    const int nrow = (lane >> 4) * 8 + (lane & 7);
    const int kadd = ((lane >> 3) & 1) * 8;
    const int trow = lane & 15;
    const int tcol = (lane >> 4) * 8;

    auto issue_kv = [&](int kt, int buf) {
        const size_t off = ((size_t)(b * SEQ + kt * 64) * NKVH + kvh) * HDIM;
        const __half* gk = Kh + off;
        const __half* gv = Vh + off;
        const uint32_t kb = sb + FKV0 + buf * KVBUF_B;
#pragma unroll
        for (int i = 0; i < 8; i++) {
            int c = i * 128 + tid;
            int r = c >> 4, ch = c & 15;
            uint32_t d = r * FP + ch * 16;
            CP_ASYNC_16(kb + d,         gk + (size_t)r * NKV + ch * 8);
            CP_ASYNC_16(kb + 17408 + d, gv + (size_t)r * NKV + ch * 8);
        }
        CP_COMMIT();
    };

    {
        const size_t qoff = ((size_t)(b * SEQ + q0) * NQH + h) * HDIM;
        const uint4* gh = (const uint4*)(Qh + qoff);
        const uint4* gl = (const uint4*)(Ql + qoff);
        for (int i = tid; i < 1024; i += 128) {
            int r = i >> 4, c = i & 15;
            *(uint4*)(sm + FQH + r * FP + c * 16) = gh[(size_t)r * 512 + c];
            *(uint4*)(sm + FQL + r * FP + c * 16) = gl[(size_t)r * 512 + c];
        }
    }

    float m0 = -1e30f, m1 = -1e30f, l0 = 0.f, l1 = 0.f;
    float oacc[16][4];
#pragma unroll
    for (int nt = 0; nt < 16; nt++)
#pragma unroll
        for (int j = 0; j < 4; j++) oacc[nt][j] = 0.f;

    const int row0 = q0 + w * 16 + (lane >> 2);
    const int cb   = 2 * (lane & 3);
    const int ktiles = qt + 1;

    issue_kv(0, 0);

    for (int kt = 0; kt < ktiles; kt++) {
        if (kt + 1 < ktiles) issue_kv(kt + 1, (kt + 1) & 1);
        else CP_COMMIT();
        CP_WAIT_1();
        __syncthreads();
        const uint32_t FKHb = FKV0 + (kt & 1) * KVBUF_B;
        const uint32_t FVHb = FKHb + 17408;

        float s[8][4];
#pragma unroll
        for (int nt = 0; nt < 8; nt++)
#pragma unroll
            for (int j = 0; j < 4; j++) s[nt][j] = 0.f;

#pragma unroll
        for (int ks = 0; ks < 8; ks++) {
            uint32_t ah[4], al[4];
            uint32_t aa = sb + FQH + (w * 16 + lrow) * FP + (ks * 16 + lk) * 2;
            LDMATRIX_X4(ah[0], ah[1], ah[2], ah[3], aa);
            LDMATRIX_X4(al[0], al[1], al[2], al[3], aa + (FQL - FQH));
            uint32_t bh[8][2];
#pragma unroll
            for (int p = 0; p < 4; p++) {
                uint32_t ba = sb + FKHb + (p * 16 + nrow) * FP + (ks * 16 + kadd) * 2;
                LDMATRIX_X4(bh[2*p][0], bh[2*p][1], bh[2*p+1][0], bh[2*p+1][1], ba);
            }
#pragma unroll
            for (int nt = 0; nt < 8; nt++) MMA_F16(s[nt], ah, bh[nt][0], bh[nt][1]);
#pragma unroll
            for (int nt = 0; nt < 8; nt++) MMA_F16(s[nt], al, bh[nt][0], bh[nt][1]);
        }

        if (kt == qt) {
            const int colb = kt * 64 + cb;
#pragma unroll
            for (int nt = 0; nt < 8; nt++) {
                int c0 = colb + 8 * nt;
                if (c0 > row0)     s[nt][0] = -1e30f;
                if (c0 + 1 > row0) s[nt][1] = -1e30f;
                if (c0 > row0 + 8)     s[nt][2] = -1e30f;
                if (c0 + 1 > row0 + 8) s[nt][3] = -1e30f;
            }
        }

        float mt0 = -1e30f, mt1 = -1e30f;
#pragma unroll
        for (int nt = 0; nt < 8; nt++) {
            mt0 = fmaxf(mt0, fmaxf(s[nt][0], s[nt][1]));
            mt1 = fmaxf(mt1, fmaxf(s[nt][2], s[nt][3]));
        }
        mt0 = fmaxf(mt0, __shfl_xor_sync(0xffffffffu, mt0, 1));
        mt0 = fmaxf(mt0, __shfl_xor_sync(0xffffffffu, mt0, 2));
        mt1 = fmaxf(mt1, __shfl_xor_sync(0xffffffffu, mt1, 1));
        mt1 = fmaxf(mt1, __shfl_xor_sync(0xffffffffu, mt1, 2));
        float mn0 = fmaxf(m0, mt0), mn1 = fmaxf(m1, mt1);
        float a0 = __expf(m0 - mn0), a1 = __expf(m1 - mn1);
        float ps0 = 0.f, ps1 = 0.f;
#pragma unroll
        for (int nt = 0; nt < 8; nt++) {
            s[nt][0] = __expf(s[nt][0] - mn0);
            s[nt][1] = __expf(s[nt][1] - mn0);
            s[nt][2] = __expf(s[nt][2] - mn1);
            s[nt][3] = __expf(s[nt][3] - mn1);
            ps0 += s[nt][0] + s[nt][1];
            ps1 += s[nt][2] + s[nt][3];
        }
        ps0 += __shfl_xor_sync(0xffffffffu, ps0, 1);
        ps0 += __shfl_xor_sync(0xffffffffu, ps0, 2);
        ps1 += __shfl_xor_sync(0xffffffffu, ps1, 1);
        ps1 += __shfl_xor_sync(0xffffffffu, ps1, 2);
        l0 = l0 * a0 + ps0;  m0 = mn0;
        l1 = l1 * a1 + ps1;  m1 = mn1;
#pragma unroll
        for (int nt = 0; nt < 16; nt++) {
            oacc[nt][0] *= a0; oacc[nt][1] *= a0;
            oacc[nt][2] *= a1; oacc[nt][3] *= a1;
        }

        // O += Ph*Vh  (Pl correction dropped: P in [0,1], rounding ~2.8e-4 RMS)
#pragma unroll
        for (int j = 0; j < 4; j++) {
            uint32_t ph[4];
            ph[0] = pack2h(s[2*j][0],   s[2*j][1]);
            ph[1] = pack2h(s[2*j][2],   s[2*j][3]);
            ph[2] = pack2h(s[2*j+1][0], s[2*j+1][1]);
            ph[3] = pack2h(s[2*j+1][2], s[2*j+1][3]);
            uint32_t vfh[8][4];
#pragma unroll
            for (int t = 0; t < 8; t++) {
                uint32_t va = sb + FVHb + (j * 16 + trow) * FP + (t * 16 + tcol) * 2;
                LDMATRIX_X4_T(vfh[t][0], vfh[t][1], vfh[t][2], vfh[t][3], va);
            }
#pragma unroll
            for (int t = 0; t < 8; t++) {
                MMA_F16(oacc[2*t],   ph, vfh[t][0], vfh[t][1]);
                MMA_F16(oacc[2*t+1], ph, vfh[t][2], vfh[t][3]);
            }
        }
        __syncthreads();
    }

    const float inv0 = 1.f / l0, inv1 = 1.f / l1;
    const size_t o0 = ((size_t)(b * SEQ + row0)) * DMODEL + h * HDIM + cb;
    const size_t o1 = ((size_t)(b * SEQ + row0 + 8)) * DMODEL + h * HDIM + cb;
#pragma unroll
    for (int nt = 0; nt < 16; nt++) {
        uint32_t hh, ll;
        split_pack_h(oacc[nt][0] * inv0, oacc[nt][1] * inv0, hh, ll);
        *(uint32_t*)(Oh + o0 + 8 * nt) = hh;
        *(uint32_t*)(Ol + o0 + 8 * nt) = ll;
        split_pack_h(oacc[nt][2] * inv1, oacc[nt][3] * inv1, hh, ll);
        *(uint32_t*)(Oh + o1 + 8 * nt) = hh;
        *(uint32_t*)(Ol + o1 + 8 * nt) = ll;
    }
}

// ---------------- host launcher ---------------------------------------------
extern "C" void kernel_launch(void* const* d_in, const int* in_sizes, int n_in,
                              void* d_out, int out_size)
{
    const float* x   = (const float*)d_in[0];
    const float* w_q = (const float*)d_in[1];
    const float* w_k = (const float*)d_in[2];
    const float* w_v = (const float*)d_in[3];
    const float* w_o = (const float*)d_in[4];
    const float* fc  = (const float*)d_in[5];
    const float* fs  = (const float*)d_in[6];
    float* out = (float*)d_out;

    __half *xh, *xl, *wqkvh, *woh, *ath, *atl, *qsh, *qsl, *ksh, *vsh;
    cudaGetSymbolAddress((void**)&xh,    g_xh);     cudaGetSymbolAddress((void**)&xl,  g_xl);
    cudaGetSymbolAddress((void**)&wqkvh, g_wqkv_h);
    cudaGetSymbolAddress((void**)&woh,   g_wot_h);
    cudaGetSymbolAddress((void**)&ath,   g_atth);   cudaGetSymbolAddress((void**)&atl, g_attl);
    cudaGetSymbolAddress((void**)&qsh,   g_qsh);    cudaGetSymbolAddress((void**)&qsl, g_qsl);
    cudaGetSymbolAddress((void**)&ksh,   g_ksh);    cudaGetSymbolAddress((void**)&vsh, g_vsh);

    cudaFuncSetAttribute(gemm_mma_kernel, cudaFuncAttributeMaxDynamicSharedMemorySize, GEMM_SMEM);
    cudaFuncSetAttribute(gemm_qkv_kernel, cudaFuncAttributeMaxDynamicSharedMemorySize, GEMM_SMEM);
    cudaFuncSetAttribute(flash_mma_kernel, cudaFuncAttributeMaxDynamicSharedMemorySize, FLASH_SMEM);

    const int M = BATCH * SEQ;  // 4096

    // all prep (4 transposes + x split) in one launch
    prep_kernel<<<N_TRANS + N_CONV, 256>>>(w_q, w_k, w_v, w_o, x,
                                           wqkvh, woh, xh, xl);

    // fused QKV projection + rope + split (one GEMM over N=6144)
    gemm_qkv_kernel<<<dim3(NQKV / 128, M / 128), 256, GEMM_SMEM>>>(
        xh, xl, wqkvh, fc, fs, qsh, qsl, ksh, vsh, DMODEL);

    // flash attention (cp.async K/V pipeline, 2 CTAs/SM, heavy tiles first)
    flash_mma_kernel<<<dim3(SEQ / 64, NQH, BATCH), 128, FLASH_SMEM>>>(
        qsh, qsl, ksh, vsh, ath, atl);

    // O projection
    gemm_mma_kernel<<<dim3(DMODEL / 128, M / 128), 256, GEMM_SMEM>>>(
        ath, atl, woh, out, M, DMODEL, DMODEL);
}